// round 11
// baseline (speedup 1.0000x reference)
#include <cuda_runtime.h>
#include <cuda_bf16.h>
#include <math.h>
#include <stdint.h>

// ---------------- problem constants ----------------------------------------
#define Bsz 8
#define Ssz 4096
#define Dsz 1024
#define Psz 2051              // 2*D + FL + 1
#define NPW 2048              // proj N handled by GEMM (gates done separately)
#define Msz (Bsz*Ssz)         // 32768

// ---------------- GEMM tiling (mma.sync bf16, CTA 128x256, 2-stage) ----------
#define TM 128
#define TN 256
#define KSLAB 64
#define NSLABS 16             // K=1024 / 64
#define ROWB 144              // smem row stride: 64 bf16 (128B) + 16B pad
#define A_TILE 18432          // 128*144
#define B_TILE 36864          // 256*144
#define A_HI 0
#define A_LO 18432
#define B_HI 36864
#define B_LO 73728
#define STAGE_BYTES 110592    // 2*A_TILE + 2*B_TILE
#define DYN_SMEM (2*STAGE_BYTES)   // 221184
#define CSW 260               // Cs fp32 stride (query/out staging)
#define CSTW 132              // CsT fp32 stride (ctx transpose staging)

// ---------------- scratch (device globals) -----------------------------------
__device__ __nv_bfloat16 g_Ahi[(long)Msz*Dsz];   // input split hi (later qmod hi)
__device__ __nv_bfloat16 g_Alo[(long)Msz*Dsz];   // input split lo (later qmod lo)
__device__ __nv_bfloat16 g_Chi[(long)Msz*Dsz];   // contextT split hi (b*s, c)
__device__ __nv_bfloat16 g_Clo[(long)Msz*Dsz];   // contextT split lo
__device__ float g_query[(long)Msz*Dsz];         // (b, s, d) natural
__device__ float g_ctx  [(long)Bsz*Dsz*Ssz];     // (b, d, s); context_all in place
__device__ float g_gates[(long)Bsz*3*Ssz];       // (b, 3, s)
__device__ __nv_bfloat16 g_WinT_hi[(long)NPW*Dsz];
__device__ __nv_bfloat16 g_WinT_lo[(long)NPW*Dsz];
__device__ __nv_bfloat16 g_Wctx_hi[(long)Dsz*Dsz];
__device__ __nv_bfloat16 g_Wctx_lo[(long)Dsz*Dsz];
__device__ __nv_bfloat16 g_WoutT_hi[(long)Dsz*Dsz];
__device__ __nv_bfloat16 g_WoutT_lo[(long)Dsz*Dsz];

// ---------------- PTX helpers -------------------------------------------------
__device__ __forceinline__ uint32_t smem_u32(const void* p) {
    uint32_t a;
    asm("{ .reg .u64 t; cvta.to.shared.u64 t, %1; cvt.u32.u64 %0, t; }" : "=r"(a) : "l"(p));
    return a;
}
#define CP16(s, g) \
    asm volatile("cp.async.cg.shared.global [%0], [%1], 16;" :: "r"(s), "l"(g) : "memory")
#define CP_COMMIT() asm volatile("cp.async.commit_group;" ::: "memory")
#define CP_WAIT0()  asm volatile("cp.async.wait_group 0;" ::: "memory")
#define CP_WAIT1()  asm volatile("cp.async.wait_group 1;" ::: "memory")

#define LDSM4(r0, r1, r2, r3, a) \
    asm volatile("ldmatrix.sync.aligned.m8n8.x4.shared.b16 {%0,%1,%2,%3}, [%4];" \
                 : "=r"(r0), "=r"(r1), "=r"(r2), "=r"(r3) : "r"(a))
#define MMA16816(d, a, b) \
    asm volatile("mma.sync.aligned.m16n8k16.row.col.f32.bf16.bf16.f32 " \
                 "{%0,%1,%2,%3}, {%4,%5,%6,%7}, {%8,%9}, {%0,%1,%2,%3};" \
                 : "+f"((d)[0]), "+f"((d)[1]), "+f"((d)[2]), "+f"((d)[3]) \
                 : "r"((a)[0]), "r"((a)[1]), "r"((a)[2]), "r"((a)[3]), \
                   "r"((b)[0]), "r"((b)[1]))

__device__ __forceinline__ float gelu_f(float x) {
    return 0.5f * x * (1.0f + erff(x * 0.70710678118654752f));
}
__device__ __forceinline__ uint32_t pack2(float v0, float v1) {
    __nv_bfloat16 a = __float2bfloat16(v0), b = __float2bfloat16(v1);
    return (uint32_t)__bfloat16_as_ushort(a) | ((uint32_t)__bfloat16_as_ushort(b) << 16);
}

// ---------------- bf16 3-pass mainloop (acc[4][8][4]) -------------------------
// Pass-major MMA order: 8 independent MMAs between reuses of each accumulator.
__device__ __forceinline__ void bf16_mainloop(
    const __nv_bfloat16* __restrict__ Ahi, const __nv_bfloat16* __restrict__ Alo,
    const __nv_bfloat16* __restrict__ Bhi, const __nv_bfloat16* __restrict__ Blo,
    long m0, long n0, uint32_t sb, float acc[4][8][4])
{
    const int tid = threadIdx.x;
    const int l = tid & 31, w = tid >> 5;
    const int wm = w >> 2, wn = w & 3;
    const int r_ = tid >> 3, u_ = tid & 7;

#define LOAD_SLAB(s, buf) do {                                                  \
        const long kb = (long)(s) * KSLAB;                                      \
        const uint32_t st = sb + (buf) * STAGE_BYTES;                           \
        _Pragma("unroll")                                                       \
        for (int it = 0; it < 4; it++) {                                        \
            const int r = it * 32 + r_;                                         \
            const uint32_t so = (uint32_t)(r * ROWB + u_ * 16);                 \
            const long ga = (m0 + r) * 1024 + kb + u_ * 8;                      \
            CP16(st + A_HI + so, Ahi + ga);                                     \
            CP16(st + A_LO + so, Alo + ga);                                     \
        }                                                                       \
        _Pragma("unroll")                                                       \
        for (int it = 0; it < 8; it++) {                                        \
            const int r = it * 32 + r_;                                         \
            const uint32_t so = (uint32_t)(r * ROWB + u_ * 16);                 \
            const long gb = (n0 + r) * 1024 + kb + u_ * 8;                      \
            CP16(st + B_HI + so, Bhi + gb);                                     \
            CP16(st + B_LO + so, Blo + gb);                                     \
        }                                                                       \
    } while (0)

    const uint32_t aoff = (uint32_t)((wm * 64 + (l & 15)) * ROWB + (l >> 4) * 16);
    const uint32_t boff = (uint32_t)((wn * 64 + ((l >> 4) * 8) + (l & 7)) * ROWB
                                     + ((l >> 3) & 1) * 16);

    LOAD_SLAB(0, 0); CP_COMMIT();
    for (int s = 0; s < NSLABS; s++) {
        if (s < NSLABS - 1) { LOAD_SLAB(s + 1, (s + 1) & 1); CP_COMMIT(); CP_WAIT1(); }
        else                { CP_WAIT0(); }
        __syncthreads();

        const uint32_t st = sb + (s & 1) * STAGE_BYTES;
        const uint32_t abh = st + A_HI + aoff;
        const uint32_t bbh = st + B_HI + boff;
#pragma unroll
        for (int ks = 0; ks < 4; ks++) {
            uint32_t bh[8][2], bl[8][2];
#pragma unroll
            for (int fp = 0; fp < 4; fp++) {
                LDSM4(bh[2*fp][0], bh[2*fp][1], bh[2*fp+1][0], bh[2*fp+1][1],
                      bbh + fp * (16 * ROWB) + ks * 32);
                LDSM4(bl[2*fp][0], bl[2*fp][1], bl[2*fp+1][0], bl[2*fp+1][1],
                      bbh + (B_LO - B_HI) + fp * (16 * ROWB) + ks * 32);
            }
#pragma unroll
            for (int fm = 0; fm < 4; fm++) {
                uint32_t ah[4], al[4];
                LDSM4(ah[0], ah[1], ah[2], ah[3], abh + fm * (16 * ROWB) + ks * 32);
                LDSM4(al[0], al[1], al[2], al[3],
                      abh + (A_LO - A_HI) + fm * (16 * ROWB) + ks * 32);
                // pass-major: 8 independent MMAs between acc reuses
#pragma unroll
                for (int fn = 0; fn < 8; fn++) MMA16816(acc[fm][fn], ah, bh[fn]);
#pragma unroll
                for (int fn = 0; fn < 8; fn++) MMA16816(acc[fm][fn], ah, bl[fn]);
#pragma unroll
                for (int fn = 0; fn < 8; fn++) MMA16816(acc[fm][fn], al, bh[fn]);
            }
        }
        __syncthreads();
    }
#undef LOAD_SLAB
}

// stage acc -> Cs[128][CSW] fp32, bias added
__device__ __forceinline__ void stage_acc(
    float* Cs, float acc[4][8][4], const float* __restrict__ bias, long n0)
{
    const int tid = threadIdx.x;
    const int l = tid & 31, w = tid >> 5;
    const int wm = w >> 2, wn = w & 3;
#pragma unroll
    for (int fm = 0; fm < 4; fm++)
#pragma unroll
        for (int fn = 0; fn < 8; fn++) {
            const int row = wm * 64 + fm * 16 + (l >> 2);
            const int col = wn * 64 + fn * 8 + (l & 3) * 2;
            const float bv0 = __ldg(&bias[n0 + col]);
            const float bv1 = __ldg(&bias[n0 + col + 1]);
            Cs[row * CSW + col]           = acc[fm][fn][0] + bv0;
            Cs[row * CSW + col + 1]       = acc[fm][fn][1] + bv1;
            Cs[(row + 8) * CSW + col]     = acc[fm][fn][2] + bv0;
            Cs[(row + 8) * CSW + col + 1] = acc[fm][fn][3] + bv1;
        }
}

// stage acc transposed -> CsT[256][CSTW], bias added
__device__ __forceinline__ void stage_acc_T(
    float* CsT, float acc[4][8][4], const float* __restrict__ bias, long n0)
{
    const int tid = threadIdx.x;
    const int l = tid & 31, w = tid >> 5;
    const int wm = w >> 2, wn = w & 3;
#pragma unroll
    for (int fm = 0; fm < 4; fm++)
#pragma unroll
        for (int fn = 0; fn < 8; fn++) {
            const int row = wm * 64 + fm * 16 + (l >> 2);
            const int col = wn * 64 + fn * 8 + (l & 3) * 2;
            const float bv0 = __ldg(&bias[n0 + col]);
            const float bv1 = __ldg(&bias[n0 + col + 1]);
            CsT[col * CSTW + row]           = acc[fm][fn][0] + bv0;
            CsT[(col + 1) * CSTW + row]     = acc[fm][fn][1] + bv1;
            CsT[col * CSTW + row + 8]       = acc[fm][fn][2] + bv0;
            CsT[(col + 1) * CSTW + row + 8] = acc[fm][fn][3] + bv1;
        }
}

// ---------------- GEMM 1: proj (query + ctx regions only) ---------------------
__global__ void __launch_bounds__(256, 1)
k_gemm_proj(const float* __restrict__ b_in)
{
    extern __shared__ char dynsm[];
    const uint32_t sb = smem_u32(dynsm);
    float acc[4][8][4] = {};
    const long m0 = (long)blockIdx.y * TM;
    const long n0 = (long)blockIdx.x * TN;

    bf16_mainloop(g_Ahi, g_Alo, g_WinT_hi, g_WinT_lo, m0, n0, sb, acc);

    const int tid = threadIdx.x;
    const long b = m0 >> 12;
    const int s0 = (int)(m0 & 4095);

    if (n0 < 1024) {
        float* Cs = (float*)dynsm;
        stage_acc(Cs, acc, b_in, n0);
        __syncthreads();
#pragma unroll
        for (int it = 0; it < 32; it++) {
            const int idx = it * 256 + tid;
            const int row = idx >> 6, c4 = (idx & 63) * 4;
            float4 v = *(float4*)&Cs[row * CSW + c4];
            *(float4*)&g_query[(m0 + row) * 1024 + n0 + c4] = v;
        }
    } else {
        float* CsT = (float*)dynsm;
        stage_acc_T(CsT, acc, b_in, n0);
        __syncthreads();
#pragma unroll
        for (int it = 0; it < 32; it++) {
            const int idx = it * 256 + tid;
            const int col = idx >> 5, u4 = (idx & 31) * 4;
            float4 v = *(float4*)&CsT[col * CSTW + u4];
            const long d = (n0 - 1024) + col;
            *(float4*)&g_ctx[((b << 10) + d) * 4096 + s0 + u4] = v;
        }
    }
}

// ---------------- gates: fp32 SIMT dots (3 cols of W_in) ----------------------
__global__ void __launch_bounds__(256)
k_gates(const float* __restrict__ input, const float* __restrict__ W_in,
        const float* __restrict__ b_in)
{
    __shared__ float red[3][8];
    const int tid = threadIdx.x;
    const long m = blockIdx.x;             // 0..32767
    const float* row = input + m * 1024;
    float a0 = 0.f, a1 = 0.f, a2 = 0.f;
#pragma unroll
    for (int it = 0; it < 4; it++) {
        const int k = it * 256 + tid;
        const float x = row[k];
        const float* wr = W_in + (long)k * Psz + 2048;
        a0 += x * wr[0]; a1 += x * wr[1]; a2 += x * wr[2];
    }
#pragma unroll
    for (int off = 16; off > 0; off >>= 1) {
        a0 += __shfl_down_sync(0xffffffffu, a0, off);
        a1 += __shfl_down_sync(0xffffffffu, a1, off);
        a2 += __shfl_down_sync(0xffffffffu, a2, off);
    }
    if ((tid & 31) == 0) {
        red[0][tid >> 5] = a0; red[1][tid >> 5] = a1; red[2][tid >> 5] = a2;
    }
    __syncthreads();
    if (tid < 3) {
        float t = 0.f;
#pragma unroll
        for (int ww = 0; ww < 8; ww++) t += red[tid][ww];
        const long b = m >> 12, s = m & 4095;
        g_gates[(b * 3 + tid) * 4096 + s] = t + b_in[2048 + tid];
    }
}

// ---------------- GEMM 2: modulator + query multiply + split ------------------
__global__ void __launch_bounds__(256, 1)
k_gemm_mod(const float* __restrict__ b_ctx)
{
    extern __shared__ char dynsm[];
    const uint32_t sb = smem_u32(dynsm);
    float acc[4][8][4] = {};
    const long m0 = (long)blockIdx.y * TM;
    const long n0 = (long)blockIdx.x * TN;

    bf16_mainloop(g_Chi, g_Clo, g_Wctx_hi, g_Wctx_lo, m0, n0, sb, acc);

    float* Cs = (float*)dynsm;
    stage_acc(Cs, acc, b_ctx, n0);
    __syncthreads();

    const int tid = threadIdx.x;
#pragma unroll
    for (int it = 0; it < 32; it++) {
        const int idx = it * 256 + tid;
        const int row = idx >> 6, c4 = (idx & 63) * 4;
        const long m = m0 + row;
        const long o = n0 + c4;
        float4 c = *(float4*)&Cs[row * CSW + c4];
        float4 q = *(const float4*)&g_query[m * 1024 + o];
        float v0 = c.x * q.x, v1 = c.y * q.y, v2 = c.z * q.z, v3 = c.w * q.w;
        __nv_bfloat16 h0 = __float2bfloat16(v0), h1 = __float2bfloat16(v1);
        __nv_bfloat16 h2 = __float2bfloat16(v2), h3 = __float2bfloat16(v3);
        uint2 hh = make_uint2(
            (uint32_t)__bfloat16_as_ushort(h0) | ((uint32_t)__bfloat16_as_ushort(h1) << 16),
            (uint32_t)__bfloat16_as_ushort(h2) | ((uint32_t)__bfloat16_as_ushort(h3) << 16));
        uint2 ll = make_uint2(
            pack2(v0 - __bfloat162float(h0), v1 - __bfloat162float(h1)),
            pack2(v2 - __bfloat162float(h2), v3 - __bfloat162float(h3)));
        *(uint2*)&g_Ahi[m * 1024 + o] = hh;
        *(uint2*)&g_Alo[m * 1024 + o] = ll;
    }
}

// ---------------- GEMM 3: out --------------------------------------------------
__global__ void __launch_bounds__(256, 1)
k_gemm_out(const float* __restrict__ b_out, float* __restrict__ out)
{
    extern __shared__ char dynsm[];
    const uint32_t sb = smem_u32(dynsm);
    float acc[4][8][4] = {};
    const long m0 = (long)blockIdx.y * TM;
    const long n0 = (long)blockIdx.x * TN;

    bf16_mainloop(g_Ahi, g_Alo, g_WoutT_hi, g_WoutT_lo, m0, n0, sb, acc);

    float* Cs = (float*)dynsm;
    stage_acc(Cs, acc, b_out, n0);
    __syncthreads();

    const int tid = threadIdx.x;
#pragma unroll
    for (int it = 0; it < 32; it++) {
        const int idx = it * 256 + tid;
        const int row = idx >> 6, c4 = (idx & 63) * 4;
        float4 v = *(float4*)&Cs[row * CSW + c4];
        *(float4*)&out[(m0 + row) * 1024 + n0 + c4] = v;
    }
}

// ---------------- prep kernels -------------------------------------------------
__global__ void k_split4(const float* __restrict__ src, __nv_bfloat16* __restrict__ hi,
                         __nv_bfloat16* __restrict__ lo, long n4)
{
    long i = (long)blockIdx.x * blockDim.x + threadIdx.x;
    if (i >= n4) return;
    float4 v = *(const float4*)(src + i * 4);
    __nv_bfloat16 h0 = __float2bfloat16(v.x), h1 = __float2bfloat16(v.y);
    __nv_bfloat16 h2 = __float2bfloat16(v.z), h3 = __float2bfloat16(v.w);
    uint2 hh = make_uint2(
        (uint32_t)__bfloat16_as_ushort(h0) | ((uint32_t)__bfloat16_as_ushort(h1) << 16),
        (uint32_t)__bfloat16_as_ushort(h2) | ((uint32_t)__bfloat16_as_ushort(h3) << 16));
    uint2 ll = make_uint2(
        pack2(v.x - __bfloat162float(h0), v.y - __bfloat162float(h1)),
        pack2(v.z - __bfloat162float(h2), v.w - __bfloat162float(h3)));
    *(uint2*)(hi + i * 4) = hh;
    *(uint2*)(lo + i * 4) = ll;
}

__global__ void k_transpose_split(const float* __restrict__ W, int ldW, int validN,
                                  __nv_bfloat16* __restrict__ Thi, __nv_bfloat16* __restrict__ Tlo)
{
    __shared__ float t[32][33];
    const int n0 = blockIdx.x * 32, k0 = blockIdx.y * 32;
    const int tx = threadIdx.x, ty = threadIdx.y;   // 32 x 8
#pragma unroll
    for (int i = 0; i < 4; i++) {
        const int k = k0 + ty + i * 8, n = n0 + tx;
        t[tx][ty + i * 8] = (n < validN) ? W[(long)k * ldW + n] : 0.0f;
    }
    __syncthreads();
#pragma unroll
    for (int i = 0; i < 4; i++) {
        const int n = n0 + ty + i * 8, k = k0 + tx;
        float v = t[ty + i * 8][tx];
        __nv_bfloat16 h = __float2bfloat16(v);
        Thi[(long)n * 1024 + k] = h;
        Tlo[(long)n * 1024 + k] = __float2bfloat16(v - __bfloat162float(h));
    }
}

__global__ void k_ctxT_split()
{
    __shared__ float t[32][33];
    const int s0 = blockIdx.x * 32, c0 = blockIdx.y * 32, b = blockIdx.z;
    const int tx = threadIdx.x, ty = threadIdx.y;   // 32 x 8
#pragma unroll
    for (int i = 0; i < 4; i++) {
        const int c = c0 + ty + i * 8, s = s0 + tx;
        t[ty + i * 8][tx] = g_ctx[((long)b * 1024 + c) * 4096 + s];
    }
    __syncthreads();
#pragma unroll
    for (int i = 0; i < 4; i++) {
        const int s = s0 + ty + i * 8, c = c0 + tx;
        float v = t[tx][ty + i * 8];
        __nv_bfloat16 h = __float2bfloat16(v);
        g_Chi[((long)b * 4096 + s) * 1024 + c] = h;
        g_Clo[((long)b * 4096 + s) * 1024 + c] = __float2bfloat16(v - __bfloat162float(h));
    }
}

// ---------------- conv chain (validated) ----------------------------------------
__global__ void __launch_bounds__(256)
k_conv(const float* __restrict__ w0, const float* __restrict__ b0,
       const float* __restrict__ w1, const float* __restrict__ b1)
{
    __shared__ float sx[8 + Ssz + 8];
    __shared__ float sc0[8 + Ssz + 9];
    __shared__ float warpsum[8];
    __shared__ float s_gval;

    const int tid = threadIdx.x;
    const int blk = blockIdx.x;
    const int b = blk >> 10;
    const int d = blk & 1023;

    float* row = g_ctx + ((long)b * Dsz + d) * Ssz;
#pragma unroll
    for (int i = 0; i < 4; i++) {
        const int e = (i * 256 + tid) * 4;
        *(float4*)&sx[8 + e] = *(const float4*)&row[e];
    }
    if (tid < 8) sx[tid] = 0.0f;
    if (tid < 8) sx[8 + Ssz + tid] = 0.0f;
    if (tid < 8) sc0[tid] = 0.0f;
    if (tid < 9) sc0[8 + Ssz + tid] = 0.0f;

    float rw0[14];
#pragma unroll
    for (int k = 0; k < 14; k++) rw0[k] = w0[d * 14 + k];
    const float bb0 = b0[d];
    __syncthreads();
#pragma unroll
    for (int i = 0; i < 16; i++) {
        const int s = i * 256 + tid;
        float a = bb0;
#pragma unroll
        for (int k = 0; k < 14; k++) a += rw0[k] * sx[s + 2 + k];
        sc0[8 + s] = gelu_f(a);
    }
    float rw1[18];
#pragma unroll
    for (int k = 0; k < 18; k++) rw1[k] = w1[d * 18 + k];
    const float bb1 = b1[d];
    __syncthreads();
    float c1v[16];
    float lsum = 0.0f;
#pragma unroll
    for (int i = 0; i < 16; i++) {
        const int s = i * 256 + tid;
        float a = bb1;
#pragma unroll
        for (int k = 0; k < 18; k++) a += rw1[k] * sc0[s + k];
        c1v[i] = gelu_f(a);
        lsum += c1v[i];
    }
    float v = lsum;
#pragma unroll
    for (int off = 16; off > 0; off >>= 1) v += __shfl_down_sync(0xffffffffu, v, off);
    if ((tid & 31) == 0) warpsum[tid >> 5] = v;
    __syncthreads();
    if (tid == 0) {
        float t = 0.0f;
#pragma unroll
        for (int w = 0; w < 8; w++) t += warpsum[w];
        s_gval = gelu_f(t * (1.0f / (float)Ssz));
    }
    __syncthreads();
    const float gmean = s_gval;

    const float* gg0 = g_gates + ((long)b * 3 + 0) * Ssz;
    const float* gg1 = g_gates + ((long)b * 3 + 1) * Ssz;
    const float* gg2 = g_gates + ((long)b * 3 + 2) * Ssz;
#pragma unroll
    for (int i = 0; i < 16; i++) {
        const int s = i * 256 + tid;
        row[s] = sc0[8 + s] * gg0[s] + c1v[i] * gg1[s] + gmean * gg2[s];
    }
}

// ---------------- launch --------------------------------------------------------
extern "C" void kernel_launch(void* const* d_in, const int* in_sizes, int n_in,
                              void* d_out, int out_size)
{
    const float* input = (const float*)d_in[0];
    const float* W_in  = (const float*)d_in[1];
    const float* b_in  = (const float*)d_in[2];
    const float* w0    = (const float*)d_in[3];
    const float* b0    = (const float*)d_in[4];
    const float* w1    = (const float*)d_in[5];
    const float* b1    = (const float*)d_in[6];
    const float* W_ctx = (const float*)d_in[7];
    const float* b_ctx = (const float*)d_in[8];
    const float* W_out = (const float*)d_in[9];
    const float* b_out = (const float*)d_in[10];
    float* out = (float*)d_out;

    cudaFuncSetAttribute(k_gemm_proj, cudaFuncAttributeMaxDynamicSharedMemorySize, DYN_SMEM);
    cudaFuncSetAttribute(k_gemm_mod,  cudaFuncAttributeMaxDynamicSharedMemorySize, DYN_SMEM);
    cudaFuncSetAttribute(k_gemm_out,  cudaFuncAttributeMaxDynamicSharedMemorySize, DYN_SMEM);

    // weight/input prep (hi/lo splits, transposes to K-major)
    {
        __nv_bfloat16 *wh, *wl;
        cudaGetSymbolAddress((void**)&wh, g_WinT_hi);
        cudaGetSymbolAddress((void**)&wl, g_WinT_lo);
        k_transpose_split<<<dim3(NPW/32, 32), dim3(32, 8)>>>(W_in, Psz, Psz, wh, wl);
        cudaGetSymbolAddress((void**)&wh, g_WoutT_hi);
        cudaGetSymbolAddress((void**)&wl, g_WoutT_lo);
        k_transpose_split<<<dim3(32, 32), dim3(32, 8)>>>(W_out, Dsz, Dsz, wh, wl);
        cudaGetSymbolAddress((void**)&wh, g_Wctx_hi);
        cudaGetSymbolAddress((void**)&wl, g_Wctx_lo);
        k_split4<<<(int)(((long)Dsz*Dsz/4 + 255)/256), 256>>>(W_ctx, wh, wl, (long)Dsz*Dsz/4);
        cudaGetSymbolAddress((void**)&wh, g_Ahi);
        cudaGetSymbolAddress((void**)&wl, g_Alo);
        k_split4<<<(int)(((long)Msz*Dsz/4 + 255)/256), 256>>>(input, wh, wl, (long)Msz*Dsz/4);
    }
    // gates (fp32, independent of proj GEMM)
    k_gates<<<Msz, 256>>>(input, W_in, b_in);
    // proj GEMM -> query/ctx
    k_gemm_proj<<<dim3(NPW/TN, Msz/TM), 256, DYN_SMEM>>>(b_in);
    // conv chain (context_all in-place in g_ctx)
    k_conv<<<Bsz * Dsz, 256>>>(w0, b0, w1, b1);
    // context transpose + split -> g_Chi/g_Clo
    k_ctxT_split<<<dim3(Ssz/32, Dsz/32, Bsz), dim3(32, 8)>>>();
    // modulator GEMM (+ query multiply; qmod split into g_Ahi/g_Alo)
    k_gemm_mod<<<dim3(Dsz/TN, Msz/TM), 256, DYN_SMEM>>>(b_ctx);
    // out GEMM
    k_gemm_out<<<dim3(Dsz/TN, Msz/TM), 256, DYN_SMEM>>>(b_out, out);
}

// round 12
// speedup vs baseline: 1.5290x; 1.5290x over previous
#include <cuda_runtime.h>
#include <cuda_bf16.h>
#include <math.h>
#include <stdint.h>

// ---------------- problem constants ----------------------------------------
#define Bsz 8
#define Ssz 4096
#define Dsz 1024
#define Psz 2051              // 2*D + FL + 1
#define NPW 2048              // proj N handled by GEMM (gates done separately)
#define Msz (Bsz*Ssz)         // 32768

// ---------------- GEMM tiling (mma.sync bf16, CTA 128x256, 512 thr) ----------
#define TM 128
#define TN 256
#define NTHR 512
#define KSLAB 64
#define NSLABS 16             // K=1024 / 64
#define ROWB 144              // smem row stride: 64 bf16 (128B) + 16B pad
#define A_TILE 18432          // 128*144
#define B_TILE 36864          // 256*144
#define A_HI 0
#define A_LO 18432
#define B_HI 36864
#define B_LO 73728
#define STAGE_BYTES 110592    // 2*A_TILE + 2*B_TILE
#define DYN_SMEM (2*STAGE_BYTES)   // 221184
#define CSW 260               // Cs fp32 stride (query/out staging)
#define CSTW 132              // CsT fp32 stride (ctx transpose staging)

// ---------------- scratch (device globals) -----------------------------------
__device__ __nv_bfloat16 g_Ahi[(long)Msz*Dsz];   // input split hi (later qmod hi)
__device__ __nv_bfloat16 g_Alo[(long)Msz*Dsz];   // input split lo (later qmod lo)
__device__ __nv_bfloat16 g_Chi[(long)Msz*Dsz];   // contextT split hi (b*s, c)
__device__ __nv_bfloat16 g_Clo[(long)Msz*Dsz];   // contextT split lo
__device__ float g_query[(long)Msz*Dsz];         // (b, s, d) natural
__device__ float g_ctx  [(long)Bsz*Dsz*Ssz];     // (b, d, s); context_all in place
__device__ float g_gates[(long)Bsz*3*Ssz];       // (b, 3, s)
__device__ __nv_bfloat16 g_WinT_hi[(long)NPW*Dsz];
__device__ __nv_bfloat16 g_WinT_lo[(long)NPW*Dsz];
__device__ __nv_bfloat16 g_Wctx_hi[(long)Dsz*Dsz];
__device__ __nv_bfloat16 g_Wctx_lo[(long)Dsz*Dsz];
__device__ __nv_bfloat16 g_WoutT_hi[(long)Dsz*Dsz];
__device__ __nv_bfloat16 g_WoutT_lo[(long)Dsz*Dsz];

// ---------------- PTX helpers -------------------------------------------------
__device__ __forceinline__ uint32_t smem_u32(const void* p) {
    uint32_t a;
    asm("{ .reg .u64 t; cvta.to.shared.u64 t, %1; cvt.u32.u64 %0, t; }" : "=r"(a) : "l"(p));
    return a;
}
#define CP16(s, g) \
    asm volatile("cp.async.cg.shared.global [%0], [%1], 16;" :: "r"(s), "l"(g) : "memory")
#define CP_COMMIT() asm volatile("cp.async.commit_group;" ::: "memory")
#define CP_WAIT0()  asm volatile("cp.async.wait_group 0;" ::: "memory")
#define CP_WAIT1()  asm volatile("cp.async.wait_group 1;" ::: "memory")

#define LDSM4(r0, r1, r2, r3, a) \
    asm volatile("ldmatrix.sync.aligned.m8n8.x4.shared.b16 {%0,%1,%2,%3}, [%4];" \
                 : "=r"(r0), "=r"(r1), "=r"(r2), "=r"(r3) : "r"(a))
#define MMA16816(d, a, b) \
    asm volatile("mma.sync.aligned.m16n8k16.row.col.f32.bf16.bf16.f32 " \
                 "{%0,%1,%2,%3}, {%4,%5,%6,%7}, {%8,%9}, {%0,%1,%2,%3};" \
                 : "+f"((d)[0]), "+f"((d)[1]), "+f"((d)[2]), "+f"((d)[3]) \
                 : "r"((a)[0]), "r"((a)[1]), "r"((a)[2]), "r"((a)[3]), \
                   "r"((b)[0]), "r"((b)[1]))

__device__ __forceinline__ float gelu_f(float x) {
    return 0.5f * x * (1.0f + erff(x * 0.70710678118654752f));
}
__device__ __forceinline__ uint32_t pack2(float v0, float v1) {
    __nv_bfloat16 a = __float2bfloat16(v0), b = __float2bfloat16(v1);
    return (uint32_t)__bfloat16_as_ushort(a) | ((uint32_t)__bfloat16_as_ushort(b) << 16);
}

// ---------------- bf16 3-pass mainloop (acc[2][8][4], 16 warps) ---------------
// Warp grid 4x4; warp tile 32x64. MMA order = R9-proven (fn inner, 3 per fn).
__device__ __forceinline__ void bf16_mainloop(
    const __nv_bfloat16* __restrict__ Ahi, const __nv_bfloat16* __restrict__ Alo,
    const __nv_bfloat16* __restrict__ Bhi, const __nv_bfloat16* __restrict__ Blo,
    long m0, long n0, uint32_t sb, float acc[2][8][4])
{
    const int tid = threadIdx.x;
    const int l = tid & 31, w = tid >> 5;
    const int wm = w >> 2, wn = w & 3;           // 4 x 4 warp grid
    const int r_ = tid >> 3, u_ = tid & 7;       // 64 rows x 8 units per pass

#define LOAD_SLAB(s, buf) do {                                                  \
        const long kb = (long)(s) * KSLAB;                                      \
        const uint32_t st = sb + (buf) * STAGE_BYTES;                           \
        _Pragma("unroll")                                                       \
        for (int it = 0; it < 2; it++) {                                        \
            const int r = it * 64 + r_;                                         \
            const uint32_t so = (uint32_t)(r * ROWB + u_ * 16);                 \
            const long ga = (m0 + r) * 1024 + kb + u_ * 8;                      \
            CP16(st + A_HI + so, Ahi + ga);                                     \
            CP16(st + A_LO + so, Alo + ga);                                     \
        }                                                                       \
        _Pragma("unroll")                                                       \
        for (int it = 0; it < 4; it++) {                                        \
            const int r = it * 64 + r_;                                         \
            const uint32_t so = (uint32_t)(r * ROWB + u_ * 16);                 \
            const long gb = (n0 + r) * 1024 + kb + u_ * 8;                      \
            CP16(st + B_HI + so, Bhi + gb);                                     \
            CP16(st + B_LO + so, Blo + gb);                                     \
        }                                                                       \
    } while (0)

    // A frag lane address: rows wm*32 + (l&15), k-half (l>>4)
    const uint32_t aoff = (uint32_t)((wm * 32 + (l & 15)) * ROWB + (l >> 4) * 16);
    // B x4 lane address: rows wn*64 + (l>>4)*8 + (l&7), k-half ((l>>3)&1)
    const uint32_t boff = (uint32_t)((wn * 64 + ((l >> 4) * 8) + (l & 7)) * ROWB
                                     + ((l >> 3) & 1) * 16);

    LOAD_SLAB(0, 0); CP_COMMIT();
    for (int s = 0; s < NSLABS; s++) {
        if (s < NSLABS - 1) { LOAD_SLAB(s + 1, (s + 1) & 1); CP_COMMIT(); CP_WAIT1(); }
        else                { CP_WAIT0(); }
        __syncthreads();

        const uint32_t st = sb + (s & 1) * STAGE_BYTES;
        const uint32_t abh = st + A_HI + aoff;
        const uint32_t bbh = st + B_HI + boff;
#pragma unroll
        for (int ks = 0; ks < 4; ks++) {
            uint32_t bh[8][2], bl[8][2];
#pragma unroll
            for (int fp = 0; fp < 4; fp++) {
                LDSM4(bh[2*fp][0], bh[2*fp][1], bh[2*fp+1][0], bh[2*fp+1][1],
                      bbh + fp * (16 * ROWB) + ks * 32);
                LDSM4(bl[2*fp][0], bl[2*fp][1], bl[2*fp+1][0], bl[2*fp+1][1],
                      bbh + (B_LO - B_HI) + fp * (16 * ROWB) + ks * 32);
            }
#pragma unroll
            for (int fm = 0; fm < 2; fm++) {
                uint32_t ah[4], al[4];
                LDSM4(ah[0], ah[1], ah[2], ah[3], abh + fm * (16 * ROWB) + ks * 32);
                LDSM4(al[0], al[1], al[2], al[3],
                      abh + (A_LO - A_HI) + fm * (16 * ROWB) + ks * 32);
#pragma unroll
                for (int fn = 0; fn < 8; fn++) {
                    MMA16816(acc[fm][fn], ah, bh[fn]);
                    MMA16816(acc[fm][fn], ah, bl[fn]);
                    MMA16816(acc[fm][fn], al, bh[fn]);
                }
            }
        }
        __syncthreads();
    }
#undef LOAD_SLAB
}

// stage acc -> Cs[128][CSW] fp32, bias added
__device__ __forceinline__ void stage_acc(
    float* Cs, float acc[2][8][4], const float* __restrict__ bias, long n0)
{
    const int tid = threadIdx.x;
    const int l = tid & 31, w = tid >> 5;
    const int wm = w >> 2, wn = w & 3;
#pragma unroll
    for (int fm = 0; fm < 2; fm++)
#pragma unroll
        for (int fn = 0; fn < 8; fn++) {
            const int row = wm * 32 + fm * 16 + (l >> 2);
            const int col = wn * 64 + fn * 8 + (l & 3) * 2;
            const float bv0 = __ldg(&bias[n0 + col]);
            const float bv1 = __ldg(&bias[n0 + col + 1]);
            Cs[row * CSW + col]           = acc[fm][fn][0] + bv0;
            Cs[row * CSW + col + 1]       = acc[fm][fn][1] + bv1;
            Cs[(row + 8) * CSW + col]     = acc[fm][fn][2] + bv0;
            Cs[(row + 8) * CSW + col + 1] = acc[fm][fn][3] + bv1;
        }
}

// stage acc transposed -> CsT[256][CSTW], bias added
__device__ __forceinline__ void stage_acc_T(
    float* CsT, float acc[2][8][4], const float* __restrict__ bias, long n0)
{
    const int tid = threadIdx.x;
    const int l = tid & 31, w = tid >> 5;
    const int wm = w >> 2, wn = w & 3;
#pragma unroll
    for (int fm = 0; fm < 2; fm++)
#pragma unroll
        for (int fn = 0; fn < 8; fn++) {
            const int row = wm * 32 + fm * 16 + (l >> 2);
            const int col = wn * 64 + fn * 8 + (l & 3) * 2;
            const float bv0 = __ldg(&bias[n0 + col]);
            const float bv1 = __ldg(&bias[n0 + col + 1]);
            CsT[col * CSTW + row]           = acc[fm][fn][0] + bv0;
            CsT[(col + 1) * CSTW + row]     = acc[fm][fn][1] + bv1;
            CsT[col * CSTW + row + 8]       = acc[fm][fn][2] + bv0;
            CsT[(col + 1) * CSTW + row + 8] = acc[fm][fn][3] + bv1;
        }
}

// ---------------- GEMM 1: proj (query + ctx regions only) ---------------------
__global__ void __launch_bounds__(NTHR, 1)
k_gemm_proj(const float* __restrict__ b_in)
{
    extern __shared__ char dynsm[];
    const uint32_t sb = smem_u32(dynsm);
    float acc[2][8][4] = {};
    const long m0 = (long)blockIdx.y * TM;
    const long n0 = (long)blockIdx.x * TN;

    bf16_mainloop(g_Ahi, g_Alo, g_WinT_hi, g_WinT_lo, m0, n0, sb, acc);

    const int tid = threadIdx.x;
    const long b = m0 >> 12;
    const int s0 = (int)(m0 & 4095);

    if (n0 < 1024) {
        float* Cs = (float*)dynsm;
        stage_acc(Cs, acc, b_in, n0);
        __syncthreads();
#pragma unroll
        for (int it = 0; it < 16; it++) {
            const int idx = it * NTHR + tid;
            const int row = idx >> 6, c4 = (idx & 63) * 4;
            float4 v = *(float4*)&Cs[row * CSW + c4];
            *(float4*)&g_query[(m0 + row) * 1024 + n0 + c4] = v;
        }
    } else {
        float* CsT = (float*)dynsm;
        stage_acc_T(CsT, acc, b_in, n0);
        __syncthreads();
#pragma unroll
        for (int it = 0; it < 16; it++) {
            const int idx = it * NTHR + tid;
            const int col = idx >> 5, u4 = (idx & 31) * 4;
            float4 v = *(float4*)&CsT[col * CSTW + u4];
            const long d = (n0 - 1024) + col;
            *(float4*)&g_ctx[((b << 10) + d) * 4096 + s0 + u4] = v;
        }
    }
}

// ---------------- gates: fp32 SIMT dots (3 cols of W_in) ----------------------
__global__ void __launch_bounds__(256)
k_gates(const float* __restrict__ input, const float* __restrict__ W_in,
        const float* __restrict__ b_in)
{
    __shared__ float red[3][8];
    const int tid = threadIdx.x;
    const long m = blockIdx.x;             // 0..32767
    const float* row = input + m * 1024;
    float a0 = 0.f, a1 = 0.f, a2 = 0.f;
#pragma unroll
    for (int it = 0; it < 4; it++) {
        const int k = it * 256 + tid;
        const float x = row[k];
        const float* wr = W_in + (long)k * Psz + 2048;
        a0 += x * wr[0]; a1 += x * wr[1]; a2 += x * wr[2];
    }
#pragma unroll
    for (int off = 16; off > 0; off >>= 1) {
        a0 += __shfl_down_sync(0xffffffffu, a0, off);
        a1 += __shfl_down_sync(0xffffffffu, a1, off);
        a2 += __shfl_down_sync(0xffffffffu, a2, off);
    }
    if ((tid & 31) == 0) {
        red[0][tid >> 5] = a0; red[1][tid >> 5] = a1; red[2][tid >> 5] = a2;
    }
    __syncthreads();
    if (tid < 3) {
        float t = 0.f;
#pragma unroll
        for (int ww = 0; ww < 8; ww++) t += red[tid][ww];
        const long b = m >> 12, s = m & 4095;
        g_gates[(b * 3 + tid) * 4096 + s] = t + b_in[2048 + tid];
    }
}

// ---------------- GEMM 2: modulator + query multiply + split ------------------
__global__ void __launch_bounds__(NTHR, 1)
k_gemm_mod(const float* __restrict__ b_ctx)
{
    extern __shared__ char dynsm[];
    const uint32_t sb = smem_u32(dynsm);
    float acc[2][8][4] = {};
    const long m0 = (long)blockIdx.y * TM;
    const long n0 = (long)blockIdx.x * TN;

    bf16_mainloop(g_Chi, g_Clo, g_Wctx_hi, g_Wctx_lo, m0, n0, sb, acc);

    float* Cs = (float*)dynsm;
    stage_acc(Cs, acc, b_ctx, n0);
    __syncthreads();

    const int tid = threadIdx.x;
#pragma unroll
    for (int it = 0; it < 16; it++) {
        const int idx = it * NTHR + tid;
        const int row = idx >> 6, c4 = (idx & 63) * 4;
        const long m = m0 + row;
        const long o = n0 + c4;
        float4 c = *(float4*)&Cs[row * CSW + c4];
        float4 q = *(const float4*)&g_query[m * 1024 + o];
        float v0 = c.x * q.x, v1 = c.y * q.y, v2 = c.z * q.z, v3 = c.w * q.w;
        __nv_bfloat16 h0 = __float2bfloat16(v0), h1 = __float2bfloat16(v1);
        __nv_bfloat16 h2 = __float2bfloat16(v2), h3 = __float2bfloat16(v3);
        uint2 hh = make_uint2(
            (uint32_t)__bfloat16_as_ushort(h0) | ((uint32_t)__bfloat16_as_ushort(h1) << 16),
            (uint32_t)__bfloat16_as_ushort(h2) | ((uint32_t)__bfloat16_as_ushort(h3) << 16));
        uint2 ll = make_uint2(
            pack2(v0 - __bfloat162float(h0), v1 - __bfloat162float(h1)),
            pack2(v2 - __bfloat162float(h2), v3 - __bfloat162float(h3)));
        *(uint2*)&g_Ahi[m * 1024 + o] = hh;
        *(uint2*)&g_Alo[m * 1024 + o] = ll;
    }
}

// ---------------- GEMM 3: out --------------------------------------------------
__global__ void __launch_bounds__(NTHR, 1)
k_gemm_out(const float* __restrict__ b_out, float* __restrict__ out)
{
    extern __shared__ char dynsm[];
    const uint32_t sb = smem_u32(dynsm);
    float acc[2][8][4] = {};
    const long m0 = (long)blockIdx.y * TM;
    const long n0 = (long)blockIdx.x * TN;

    bf16_mainloop(g_Ahi, g_Alo, g_WoutT_hi, g_WoutT_lo, m0, n0, sb, acc);

    float* Cs = (float*)dynsm;
    stage_acc(Cs, acc, b_out, n0);
    __syncthreads();

    const int tid = threadIdx.x;
#pragma unroll
    for (int it = 0; it < 16; it++) {
        const int idx = it * NTHR + tid;
        const int row = idx >> 6, c4 = (idx & 63) * 4;
        float4 v = *(float4*)&Cs[row * CSW + c4];
        *(float4*)&out[(m0 + row) * 1024 + n0 + c4] = v;
    }
}

// ---------------- prep kernels -------------------------------------------------
__global__ void k_split4(const float* __restrict__ src, __nv_bfloat16* __restrict__ hi,
                         __nv_bfloat16* __restrict__ lo, long n4)
{
    long i = (long)blockIdx.x * blockDim.x + threadIdx.x;
    if (i >= n4) return;
    float4 v = *(const float4*)(src + i * 4);
    __nv_bfloat16 h0 = __float2bfloat16(v.x), h1 = __float2bfloat16(v.y);
    __nv_bfloat16 h2 = __float2bfloat16(v.z), h3 = __float2bfloat16(v.w);
    uint2 hh = make_uint2(
        (uint32_t)__bfloat16_as_ushort(h0) | ((uint32_t)__bfloat16_as_ushort(h1) << 16),
        (uint32_t)__bfloat16_as_ushort(h2) | ((uint32_t)__bfloat16_as_ushort(h3) << 16));
    uint2 ll = make_uint2(
        pack2(v.x - __bfloat162float(h0), v.y - __bfloat162float(h1)),
        pack2(v.z - __bfloat162float(h2), v.w - __bfloat162float(h3)));
    *(uint2*)(hi + i * 4) = hh;
    *(uint2*)(lo + i * 4) = ll;
}

__global__ void k_transpose_split(const float* __restrict__ W, int ldW, int validN,
                                  __nv_bfloat16* __restrict__ Thi, __nv_bfloat16* __restrict__ Tlo)
{
    __shared__ float t[32][33];
    const int n0 = blockIdx.x * 32, k0 = blockIdx.y * 32;
    const int tx = threadIdx.x, ty = threadIdx.y;   // 32 x 8
#pragma unroll
    for (int i = 0; i < 4; i++) {
        const int k = k0 + ty + i * 8, n = n0 + tx;
        t[tx][ty + i * 8] = (n < validN) ? W[(long)k * ldW + n] : 0.0f;
    }
    __syncthreads();
#pragma unroll
    for (int i = 0; i < 4; i++) {
        const int n = n0 + ty + i * 8, k = k0 + tx;
        float v = t[ty + i * 8][tx];
        __nv_bfloat16 h = __float2bfloat16(v);
        Thi[(long)n * 1024 + k] = h;
        Tlo[(long)n * 1024 + k] = __float2bfloat16(v - __bfloat162float(h));
    }
}

__global__ void k_ctxT_split()
{
    __shared__ float t[32][33];
    const int s0 = blockIdx.x * 32, c0 = blockIdx.y * 32, b = blockIdx.z;
    const int tx = threadIdx.x, ty = threadIdx.y;   // 32 x 8
#pragma unroll
    for (int i = 0; i < 4; i++) {
        const int c = c0 + ty + i * 8, s = s0 + tx;
        t[ty + i * 8][tx] = g_ctx[((long)b * 1024 + c) * 4096 + s];
    }
    __syncthreads();
#pragma unroll
    for (int i = 0; i < 4; i++) {
        const int s = s0 + ty + i * 8, c = c0 + tx;
        float v = t[tx][ty + i * 8];
        __nv_bfloat16 h = __float2bfloat16(v);
        g_Chi[((long)b * 4096 + s) * 1024 + c] = h;
        g_Clo[((long)b * 4096 + s) * 1024 + c] = __float2bfloat16(v - __bfloat162float(h));
    }
}

// ---------------- conv chain (validated) ----------------------------------------
__global__ void __launch_bounds__(256)
k_conv(const float* __restrict__ w0, const float* __restrict__ b0,
       const float* __restrict__ w1, const float* __restrict__ b1)
{
    __shared__ float sx[8 + Ssz + 8];
    __shared__ float sc0[8 + Ssz + 9];
    __shared__ float warpsum[8];
    __shared__ float s_gval;

    const int tid = threadIdx.x;
    const int blk = blockIdx.x;
    const int b = blk >> 10;
    const int d = blk & 1023;

    float* row = g_ctx + ((long)b * Dsz + d) * Ssz;
#pragma unroll
    for (int i = 0; i < 4; i++) {
        const int e = (i * 256 + tid) * 4;
        *(float4*)&sx[8 + e] = *(const float4*)&row[e];
    }
    if (tid < 8) sx[tid] = 0.0f;
    if (tid < 8) sx[8 + Ssz + tid] = 0.0f;
    if (tid < 8) sc0[tid] = 0.0f;
    if (tid < 9) sc0[8 + Ssz + tid] = 0.0f;

    float rw0[14];
#pragma unroll
    for (int k = 0; k < 14; k++) rw0[k] = w0[d * 14 + k];
    const float bb0 = b0[d];
    __syncthreads();
#pragma unroll
    for (int i = 0; i < 16; i++) {
        const int s = i * 256 + tid;
        float a = bb0;
#pragma unroll
        for (int k = 0; k < 14; k++) a += rw0[k] * sx[s + 2 + k];
        sc0[8 + s] = gelu_f(a);
    }
    float rw1[18];
#pragma unroll
    for (int k = 0; k < 18; k++) rw1[k] = w1[d * 18 + k];
    const float bb1 = b1[d];
    __syncthreads();
    float c1v[16];
    float lsum = 0.0f;
#pragma unroll
    for (int i = 0; i < 16; i++) {
        const int s = i * 256 + tid;
        float a = bb1;
#pragma unroll
        for (int k = 0; k < 18; k++) a += rw1[k] * sc0[s + k];
        c1v[i] = gelu_f(a);
        lsum += c1v[i];
    }
    float v = lsum;
#pragma unroll
    for (int off = 16; off > 0; off >>= 1) v += __shfl_down_sync(0xffffffffu, v, off);
    if ((tid & 31) == 0) warpsum[tid >> 5] = v;
    __syncthreads();
    if (tid == 0) {
        float t = 0.0f;
#pragma unroll
        for (int w = 0; w < 8; w++) t += warpsum[w];
        s_gval = gelu_f(t * (1.0f / (float)Ssz));
    }
    __syncthreads();
    const float gmean = s_gval;

    const float* gg0 = g_gates + ((long)b * 3 + 0) * Ssz;
    const float* gg1 = g_gates + ((long)b * 3 + 1) * Ssz;
    const float* gg2 = g_gates + ((long)b * 3 + 2) * Ssz;
#pragma unroll
    for (int i = 0; i < 16; i++) {
        const int s = i * 256 + tid;
        row[s] = sc0[8 + s] * gg0[s] + c1v[i] * gg1[s] + gmean * gg2[s];
    }
}

// ---------------- launch --------------------------------------------------------
extern "C" void kernel_launch(void* const* d_in, const int* in_sizes, int n_in,
                              void* d_out, int out_size)
{
    const float* input = (const float*)d_in[0];
    const float* W_in  = (const float*)d_in[1];
    const float* b_in  = (const float*)d_in[2];
    const float* w0    = (const float*)d_in[3];
    const float* b0    = (const float*)d_in[4];
    const float* w1    = (const float*)d_in[5];
    const float* b1    = (const float*)d_in[6];
    const float* W_ctx = (const float*)d_in[7];
    const float* b_ctx = (const float*)d_in[8];
    const float* W_out = (const float*)d_in[9];
    const float* b_out = (const float*)d_in[10];
    float* out = (float*)d_out;

    cudaFuncSetAttribute(k_gemm_proj, cudaFuncAttributeMaxDynamicSharedMemorySize, DYN_SMEM);
    cudaFuncSetAttribute(k_gemm_mod,  cudaFuncAttributeMaxDynamicSharedMemorySize, DYN_SMEM);
    cudaFuncSetAttribute(k_gemm_out,  cudaFuncAttributeMaxDynamicSharedMemorySize, DYN_SMEM);

    // weight/input prep (hi/lo splits, transposes to K-major)
    {
        __nv_bfloat16 *wh, *wl;
        cudaGetSymbolAddress((void**)&wh, g_WinT_hi);
        cudaGetSymbolAddress((void**)&wl, g_WinT_lo);
        k_transpose_split<<<dim3(NPW/32, 32), dim3(32, 8)>>>(W_in, Psz, Psz, wh, wl);
        cudaGetSymbolAddress((void**)&wh, g_WoutT_hi);
        cudaGetSymbolAddress((void**)&wl, g_WoutT_lo);
        k_transpose_split<<<dim3(32, 32), dim3(32, 8)>>>(W_out, Dsz, Dsz, wh, wl);
        cudaGetSymbolAddress((void**)&wh, g_Wctx_hi);
        cudaGetSymbolAddress((void**)&wl, g_Wctx_lo);
        k_split4<<<(int)(((long)Dsz*Dsz/4 + 255)/256), 256>>>(W_ctx, wh, wl, (long)Dsz*Dsz/4);
        cudaGetSymbolAddress((void**)&wh, g_Ahi);
        cudaGetSymbolAddress((void**)&wl, g_Alo);
        k_split4<<<(int)(((long)Msz*Dsz/4 + 255)/256), 256>>>(input, wh, wl, (long)Msz*Dsz/4);
    }
    // gates (fp32, independent of proj GEMM)
    k_gates<<<Msz, 256>>>(input, W_in, b_in);
    // proj GEMM -> query/ctx
    k_gemm_proj<<<dim3(NPW/TN, Msz/TM), NTHR, DYN_SMEM>>>(b_in);
    // conv chain (context_all in-place in g_ctx)
    k_conv<<<Bsz * Dsz, 256>>>(w0, b0, w1, b1);
    // context transpose + split -> g_Chi/g_Clo
    k_ctxT_split<<<dim3(Ssz/32, Dsz/32, Bsz), dim3(32, 8)>>>();
    // modulator GEMM (+ query multiply; qmod split into g_Ahi/g_Alo)
    k_gemm_mod<<<dim3(Dsz/TN, Msz/TM), NTHR, DYN_SMEM>>>(b_ctx);
    // out GEMM
    k_gemm_out<<<dim3(Dsz/TN, Msz/TM), NTHR, DYN_SMEM>>>(b_out, out);
}

// round 13
// speedup vs baseline: 1.9671x; 1.2865x over previous
#include <cuda_runtime.h>
#include <cuda_fp16.h>
#include <math.h>
#include <stdint.h>

// ---------------- problem constants ----------------------------------------
#define Bsz 8
#define Ssz 4096
#define Dsz 1024
#define Psz 2051              // 2*D + FL + 1
#define NPW 2048              // proj N handled by GEMM (gates done separately)
#define Msz (Bsz*Ssz)         // 32768

// ---------------- GEMM tiling (mma.sync fp16 2-pass, CTA 128x256) ------------
#define TM 128
#define TN 256
#define KSLAB 64
#define NSLABS 16             // K=1024 / 64
#define ROWB 144              // smem row stride: 64 fp16 (128B) + 16B pad
#define A_HI 0                // A tile: 128*144 = 18432
#define B_HI 18432
#define B_LO 55296            // B tiles: 256*144 = 36864 each
#define STAGE_BYTES 92160     // A + 2*B
#define DYN_SMEM (2*STAGE_BYTES)   // 184320
#define CSW 260               // Cs fp32 stride (query/out staging)
#define CSTW 132              // CsT fp32 stride (ctx transpose staging)

// ---------------- scratch (device globals) -----------------------------------
__device__ __half g_Ain [(long)Msz*Dsz];         // input fp16 (later qmod fp16)
__device__ __half g_Ctx16[(long)Msz*Dsz];        // contextT fp16 (b*s, c)
__device__ float g_query[(long)Msz*Dsz];         // (b, s, d) natural
__device__ float g_ctx  [(long)Bsz*Dsz*Ssz];     // (b, d, s); context_all in place
__device__ float g_gates[(long)Bsz*3*Ssz];       // (b, 3, s)
__device__ __half g_WinT_hi[(long)NPW*Dsz];
__device__ __half g_WinT_lo[(long)NPW*Dsz];
__device__ __half g_Wctx_hi[(long)Dsz*Dsz];
__device__ __half g_Wctx_lo[(long)Dsz*Dsz];
__device__ __half g_WoutT_hi[(long)Dsz*Dsz];
__device__ __half g_WoutT_lo[(long)Dsz*Dsz];

// ---------------- PTX helpers -------------------------------------------------
__device__ __forceinline__ uint32_t smem_u32(const void* p) {
    uint32_t a;
    asm("{ .reg .u64 t; cvta.to.shared.u64 t, %1; cvt.u32.u64 %0, t; }" : "=r"(a) : "l"(p));
    return a;
}
#define CP16(s, g) \
    asm volatile("cp.async.cg.shared.global [%0], [%1], 16;" :: "r"(s), "l"(g) : "memory")
#define CP_COMMIT() asm volatile("cp.async.commit_group;" ::: "memory")
#define CP_WAIT0()  asm volatile("cp.async.wait_group 0;" ::: "memory")
#define CP_WAIT1()  asm volatile("cp.async.wait_group 1;" ::: "memory")

#define LDSM4(r0, r1, r2, r3, a) \
    asm volatile("ldmatrix.sync.aligned.m8n8.x4.shared.b16 {%0,%1,%2,%3}, [%4];" \
                 : "=r"(r0), "=r"(r1), "=r"(r2), "=r"(r3) : "r"(a))
#define MMA16816(d, a, b) \
    asm volatile("mma.sync.aligned.m16n8k16.row.col.f32.f16.f16.f32 " \
                 "{%0,%1,%2,%3}, {%4,%5,%6,%7}, {%8,%9}, {%0,%1,%2,%3};" \
                 : "+f"((d)[0]), "+f"((d)[1]), "+f"((d)[2]), "+f"((d)[3]) \
                 : "r"((a)[0]), "r"((a)[1]), "r"((a)[2]), "r"((a)[3]), \
                   "r"((b)[0]), "r"((b)[1]))

__device__ __forceinline__ float gelu_f(float x) {
    return 0.5f * x * (1.0f + erff(x * 0.70710678118654752f));
}
__device__ __forceinline__ uint32_t pack2h(float v0, float v1) {
    __half a = __float2half(v0), b = __float2half(v1);
    return (uint32_t)__half_as_ushort(a) | ((uint32_t)__half_as_ushort(b) << 16);
}

// ---------------- fp16 2-pass mainloop (acc[4][8][4], 8 warps) ----------------
// A fp16 (single term), B fp16 hi+lo. Passes: A*Bhi + A*Blo.
__device__ __forceinline__ void fp16_mainloop(
    const __half* __restrict__ A,
    const __half* __restrict__ Bhi, const __half* __restrict__ Blo,
    long m0, long n0, uint32_t sb, float acc[4][8][4])
{
    const int tid = threadIdx.x;
    const int l = tid & 31, w = tid >> 5;
    const int wm = w >> 2, wn = w & 3;
    const int r_ = tid >> 3, u_ = tid & 7;

#define LOAD_SLAB(s, buf) do {                                                  \
        const long kb = (long)(s) * KSLAB;                                      \
        const uint32_t st = sb + (buf) * STAGE_BYTES;                           \
        _Pragma("unroll")                                                       \
        for (int it = 0; it < 4; it++) {                                        \
            const int r = it * 32 + r_;                                         \
            const uint32_t so = (uint32_t)(r * ROWB + u_ * 16);                 \
            const long ga = (m0 + r) * 1024 + kb + u_ * 8;                      \
            CP16(st + A_HI + so, A + ga);                                       \
        }                                                                       \
        _Pragma("unroll")                                                       \
        for (int it = 0; it < 8; it++) {                                        \
            const int r = it * 32 + r_;                                         \
            const uint32_t so = (uint32_t)(r * ROWB + u_ * 16);                 \
            const long gb = (n0 + r) * 1024 + kb + u_ * 8;                      \
            CP16(st + B_HI + so, Bhi + gb);                                     \
            CP16(st + B_LO + so, Blo + gb);                                     \
        }                                                                       \
    } while (0)

    const uint32_t aoff = (uint32_t)((wm * 64 + (l & 15)) * ROWB + (l >> 4) * 16);
    const uint32_t boff = (uint32_t)((wn * 64 + ((l >> 4) * 8) + (l & 7)) * ROWB
                                     + ((l >> 3) & 1) * 16);

    LOAD_SLAB(0, 0); CP_COMMIT();
    for (int s = 0; s < NSLABS; s++) {
        if (s < NSLABS - 1) { LOAD_SLAB(s + 1, (s + 1) & 1); CP_COMMIT(); CP_WAIT1(); }
        else                { CP_WAIT0(); }
        __syncthreads();

        const uint32_t st = sb + (s & 1) * STAGE_BYTES;
        const uint32_t abh = st + A_HI + aoff;
        const uint32_t bbh = st + B_HI + boff;
#pragma unroll
        for (int ks = 0; ks < 4; ks++) {
            uint32_t bh[8][2], bl[8][2];
#pragma unroll
            for (int fp = 0; fp < 4; fp++) {
                LDSM4(bh[2*fp][0], bh[2*fp][1], bh[2*fp+1][0], bh[2*fp+1][1],
                      bbh + fp * (16 * ROWB) + ks * 32);
                LDSM4(bl[2*fp][0], bl[2*fp][1], bl[2*fp+1][0], bl[2*fp+1][1],
                      bbh + (B_LO - B_HI) + fp * (16 * ROWB) + ks * 32);
            }
#pragma unroll
            for (int fm = 0; fm < 4; fm++) {
                uint32_t ah[4];
                LDSM4(ah[0], ah[1], ah[2], ah[3], abh + fm * (16 * ROWB) + ks * 32);
#pragma unroll
                for (int fn = 0; fn < 8; fn++) {
                    MMA16816(acc[fm][fn], ah, bh[fn]);
                    MMA16816(acc[fm][fn], ah, bl[fn]);
                }
            }
        }
        __syncthreads();
    }
#undef LOAD_SLAB
}

// stage acc -> Cs[128][CSW] fp32, bias added
__device__ __forceinline__ void stage_acc(
    float* Cs, float acc[4][8][4], const float* __restrict__ bias, long n0)
{
    const int tid = threadIdx.x;
    const int l = tid & 31, w = tid >> 5;
    const int wm = w >> 2, wn = w & 3;
#pragma unroll
    for (int fm = 0; fm < 4; fm++)
#pragma unroll
        for (int fn = 0; fn < 8; fn++) {
            const int row = wm * 64 + fm * 16 + (l >> 2);
            const int col = wn * 64 + fn * 8 + (l & 3) * 2;
            const float bv0 = __ldg(&bias[n0 + col]);
            const float bv1 = __ldg(&bias[n0 + col + 1]);
            Cs[row * CSW + col]           = acc[fm][fn][0] + bv0;
            Cs[row * CSW + col + 1]       = acc[fm][fn][1] + bv1;
            Cs[(row + 8) * CSW + col]     = acc[fm][fn][2] + bv0;
            Cs[(row + 8) * CSW + col + 1] = acc[fm][fn][3] + bv1;
        }
}

// stage acc transposed -> CsT[256][CSTW], bias added
__device__ __forceinline__ void stage_acc_T(
    float* CsT, float acc[4][8][4], const float* __restrict__ bias, long n0)
{
    const int tid = threadIdx.x;
    const int l = tid & 31, w = tid >> 5;
    const int wm = w >> 2, wn = w & 3;
#pragma unroll
    for (int fm = 0; fm < 4; fm++)
#pragma unroll
        for (int fn = 0; fn < 8; fn++) {
            const int row = wm * 64 + fm * 16 + (l >> 2);
            const int col = wn * 64 + fn * 8 + (l & 3) * 2;
            const float bv0 = __ldg(&bias[n0 + col]);
            const float bv1 = __ldg(&bias[n0 + col + 1]);
            CsT[col * CSTW + row]           = acc[fm][fn][0] + bv0;
            CsT[(col + 1) * CSTW + row]     = acc[fm][fn][1] + bv1;
            CsT[col * CSTW + row + 8]       = acc[fm][fn][2] + bv0;
            CsT[(col + 1) * CSTW + row + 8] = acc[fm][fn][3] + bv1;
        }
}

// ---------------- GEMM 1: proj (query + ctx regions only) ---------------------
__global__ void __launch_bounds__(256, 1)
k_gemm_proj(const float* __restrict__ b_in)
{
    extern __shared__ char dynsm[];
    const uint32_t sb = smem_u32(dynsm);
    float acc[4][8][4] = {};
    const long m0 = (long)blockIdx.y * TM;
    const long n0 = (long)blockIdx.x * TN;

    fp16_mainloop(g_Ain, g_WinT_hi, g_WinT_lo, m0, n0, sb, acc);

    const int tid = threadIdx.x;
    const long b = m0 >> 12;
    const int s0 = (int)(m0 & 4095);

    if (n0 < 1024) {
        float* Cs = (float*)dynsm;
        stage_acc(Cs, acc, b_in, n0);
        __syncthreads();
#pragma unroll
        for (int it = 0; it < 32; it++) {
            const int idx = it * 256 + tid;
            const int row = idx >> 6, c4 = (idx & 63) * 4;
            float4 v = *(float4*)&Cs[row * CSW + c4];
            *(float4*)&g_query[(m0 + row) * 1024 + n0 + c4] = v;
        }
    } else {
        float* CsT = (float*)dynsm;
        stage_acc_T(CsT, acc, b_in, n0);
        __syncthreads();
#pragma unroll
        for (int it = 0; it < 32; it++) {
            const int idx = it * 256 + tid;
            const int col = idx >> 5, u4 = (idx & 31) * 4;
            float4 v = *(float4*)&CsT[col * CSTW + u4];
            const long d = (n0 - 1024) + col;
            *(float4*)&g_ctx[((b << 10) + d) * 4096 + s0 + u4] = v;
        }
    }
}

// ---------------- gates: fp32 SIMT dots (3 cols of W_in) ----------------------
__global__ void __launch_bounds__(256)
k_gates(const float* __restrict__ input, const float* __restrict__ W_in,
        const float* __restrict__ b_in)
{
    __shared__ float red[3][8];
    const int tid = threadIdx.x;
    const long m = blockIdx.x;             // 0..32767
    const float* row = input + m * 1024;
    float a0 = 0.f, a1 = 0.f, a2 = 0.f;
#pragma unroll
    for (int it = 0; it < 4; it++) {
        const int k = it * 256 + tid;
        const float x = row[k];
        const float* wr = W_in + (long)k * Psz + 2048;
        a0 += x * wr[0]; a1 += x * wr[1]; a2 += x * wr[2];
    }
#pragma unroll
    for (int off = 16; off > 0; off >>= 1) {
        a0 += __shfl_down_sync(0xffffffffu, a0, off);
        a1 += __shfl_down_sync(0xffffffffu, a1, off);
        a2 += __shfl_down_sync(0xffffffffu, a2, off);
    }
    if ((tid & 31) == 0) {
        red[0][tid >> 5] = a0; red[1][tid >> 5] = a1; red[2][tid >> 5] = a2;
    }
    __syncthreads();
    if (tid < 3) {
        float t = 0.f;
#pragma unroll
        for (int ww = 0; ww < 8; ww++) t += red[tid][ww];
        const long b = m >> 12, s = m & 4095;
        g_gates[(b * 3 + tid) * 4096 + s] = t + b_in[2048 + tid];
    }
}

// ---------------- GEMM 2: modulator + query multiply ---------------------------
__global__ void __launch_bounds__(256, 1)
k_gemm_mod(const float* __restrict__ b_ctx)
{
    extern __shared__ char dynsm[];
    const uint32_t sb = smem_u32(dynsm);
    float acc[4][8][4] = {};
    const long m0 = (long)blockIdx.y * TM;
    const long n0 = (long)blockIdx.x * TN;

    fp16_mainloop(g_Ctx16, g_Wctx_hi, g_Wctx_lo, m0, n0, sb, acc);

    float* Cs = (float*)dynsm;
    stage_acc(Cs, acc, b_ctx, n0);
    __syncthreads();

    const int tid = threadIdx.x;
#pragma unroll
    for (int it = 0; it < 32; it++) {
        const int idx = it * 256 + tid;
        const int row = idx >> 6, c4 = (idx & 63) * 4;
        const long m = m0 + row;
        const long o = n0 + c4;
        float4 c = *(float4*)&Cs[row * CSW + c4];
        float4 q = *(const float4*)&g_query[m * 1024 + o];
        uint2 hh = make_uint2(pack2h(c.x * q.x, c.y * q.y),
                              pack2h(c.z * q.z, c.w * q.w));
        *(uint2*)&g_Ain[m * 1024 + o] = hh;
    }
}

// ---------------- GEMM 3: out --------------------------------------------------
__global__ void __launch_bounds__(256, 1)
k_gemm_out(const float* __restrict__ b_out, float* __restrict__ out)
{
    extern __shared__ char dynsm[];
    const uint32_t sb = smem_u32(dynsm);
    float acc[4][8][4] = {};
    const long m0 = (long)blockIdx.y * TM;
    const long n0 = (long)blockIdx.x * TN;

    fp16_mainloop(g_Ain, g_WoutT_hi, g_WoutT_lo, m0, n0, sb, acc);

    float* Cs = (float*)dynsm;
    stage_acc(Cs, acc, b_out, n0);
    __syncthreads();

    const int tid = threadIdx.x;
#pragma unroll
    for (int it = 0; it < 32; it++) {
        const int idx = it * 256 + tid;
        const int row = idx >> 6, c4 = (idx & 63) * 4;
        float4 v = *(float4*)&Cs[row * CSW + c4];
        *(float4*)&out[(m0 + row) * 1024 + n0 + c4] = v;
    }
}

// ---------------- prep kernels -------------------------------------------------
// fp32 -> fp16 (A side, single term)
__global__ void k_cvt4(const float* __restrict__ src, __half* __restrict__ dst, long n4)
{
    long i = (long)blockIdx.x * blockDim.x + threadIdx.x;
    if (i >= n4) return;
    float4 v = *(const float4*)(src + i * 4);
    uint2 hh = make_uint2(pack2h(v.x, v.y), pack2h(v.z, v.w));
    *(uint2*)(dst + i * 4) = hh;
}

// fp32 -> fp16 hi/lo (B side, elementwise; for W_ctx which is already (o, c))
__global__ void k_split4h(const float* __restrict__ src, __half* __restrict__ hi,
                          __half* __restrict__ lo, long n4)
{
    long i = (long)blockIdx.x * blockDim.x + threadIdx.x;
    if (i >= n4) return;
    float4 v = *(const float4*)(src + i * 4);
    __half h0 = __float2half(v.x), h1 = __float2half(v.y);
    __half h2 = __float2half(v.z), h3 = __float2half(v.w);
    uint2 hh = make_uint2(
        (uint32_t)__half_as_ushort(h0) | ((uint32_t)__half_as_ushort(h1) << 16),
        (uint32_t)__half_as_ushort(h2) | ((uint32_t)__half_as_ushort(h3) << 16));
    uint2 ll = make_uint2(
        pack2h(v.x - __half2float(h0), v.y - __half2float(h1)),
        pack2h(v.z - __half2float(h2), v.w - __half2float(h3)));
    *(uint2*)(hi + i * 4) = hh;
    *(uint2*)(lo + i * 4) = ll;
}

// transpose W[k][n] (ldW cols, 1024 k-rows) -> T[n][k] fp16 hi/lo; n >= validN -> 0
__global__ void k_transpose_split(const float* __restrict__ W, int ldW, int validN,
                                  __half* __restrict__ Thi, __half* __restrict__ Tlo)
{
    __shared__ float t[32][33];
    const int n0 = blockIdx.x * 32, k0 = blockIdx.y * 32;
    const int tx = threadIdx.x, ty = threadIdx.y;   // 32 x 8
#pragma unroll
    for (int i = 0; i < 4; i++) {
        const int k = k0 + ty + i * 8, n = n0 + tx;
        t[tx][ty + i * 8] = (n < validN) ? W[(long)k * ldW + n] : 0.0f;
    }
    __syncthreads();
#pragma unroll
    for (int i = 0; i < 4; i++) {
        const int n = n0 + ty + i * 8, k = k0 + tx;
        float v = t[ty + i * 8][tx];
        __half h = __float2half(v);
        Thi[(long)n * 1024 + k] = h;
        Tlo[(long)n * 1024 + k] = __float2half(v - __half2float(h));
    }
}

// context (b, c, s) fp32 -> ctxT (b*s, c) fp16 (single term)
__global__ void k_ctxT_cvt()
{
    __shared__ float t[32][33];
    const int s0 = blockIdx.x * 32, c0 = blockIdx.y * 32, b = blockIdx.z;
    const int tx = threadIdx.x, ty = threadIdx.y;   // 32 x 8
#pragma unroll
    for (int i = 0; i < 4; i++) {
        const int c = c0 + ty + i * 8, s = s0 + tx;
        t[ty + i * 8][tx] = g_ctx[((long)b * 1024 + c) * 4096 + s];
    }
    __syncthreads();
#pragma unroll
    for (int i = 0; i < 4; i++) {
        const int s = s0 + ty + i * 8, c = c0 + tx;
        g_Ctx16[((long)b * 4096 + s) * 1024 + c] = __float2half(t[tx][ty + i * 8]);
    }
}

// ---------------- conv chain (validated) ----------------------------------------
__global__ void __launch_bounds__(256)
k_conv(const float* __restrict__ w0, const float* __restrict__ b0,
       const float* __restrict__ w1, const float* __restrict__ b1)
{
    __shared__ float sx[8 + Ssz + 8];
    __shared__ float sc0[8 + Ssz + 9];
    __shared__ float warpsum[8];
    __shared__ float s_gval;

    const int tid = threadIdx.x;
    const int blk = blockIdx.x;
    const int b = blk >> 10;
    const int d = blk & 1023;

    float* row = g_ctx + ((long)b * Dsz + d) * Ssz;
#pragma unroll
    for (int i = 0; i < 4; i++) {
        const int e = (i * 256 + tid) * 4;
        *(float4*)&sx[8 + e] = *(const float4*)&row[e];
    }
    if (tid < 8) sx[tid] = 0.0f;
    if (tid < 8) sx[8 + Ssz + tid] = 0.0f;
    if (tid < 8) sc0[tid] = 0.0f;
    if (tid < 9) sc0[8 + Ssz + tid] = 0.0f;

    float rw0[14];
#pragma unroll
    for (int k = 0; k < 14; k++) rw0[k] = w0[d * 14 + k];
    const float bb0 = b0[d];
    __syncthreads();
#pragma unroll
    for (int i = 0; i < 16; i++) {
        const int s = i * 256 + tid;
        float a = bb0;
#pragma unroll
        for (int k = 0; k < 14; k++) a += rw0[k] * sx[s + 2 + k];
        sc0[8 + s] = gelu_f(a);
    }
    float rw1[18];
#pragma unroll
    for (int k = 0; k < 18; k++) rw1[k] = w1[d * 18 + k];
    const float bb1 = b1[d];
    __syncthreads();
    float c1v[16];
    float lsum = 0.0f;
#pragma unroll
    for (int i = 0; i < 16; i++) {
        const int s = i * 256 + tid;
        float a = bb1;
#pragma unroll
        for (int k = 0; k < 18; k++) a += rw1[k] * sc0[s + k];
        c1v[i] = gelu_f(a);
        lsum += c1v[i];
    }
    float v = lsum;
#pragma unroll
    for (int off = 16; off > 0; off >>= 1) v += __shfl_down_sync(0xffffffffu, v, off);
    if ((tid & 31) == 0) warpsum[tid >> 5] = v;
    __syncthreads();
    if (tid == 0) {
        float t = 0.0f;
#pragma unroll
        for (int w = 0; w < 8; w++) t += warpsum[w];
        s_gval = gelu_f(t * (1.0f / (float)Ssz));
    }
    __syncthreads();
    const float gmean = s_gval;

    const float* gg0 = g_gates + ((long)b * 3 + 0) * Ssz;
    const float* gg1 = g_gates + ((long)b * 3 + 1) * Ssz;
    const float* gg2 = g_gates + ((long)b * 3 + 2) * Ssz;
#pragma unroll
    for (int i = 0; i < 16; i++) {
        const int s = i * 256 + tid;
        row[s] = sc0[8 + s] * gg0[s] + c1v[i] * gg1[s] + gmean * gg2[s];
    }
}

// ---------------- launch --------------------------------------------------------
extern "C" void kernel_launch(void* const* d_in, const int* in_sizes, int n_in,
                              void* d_out, int out_size)
{
    const float* input = (const float*)d_in[0];
    const float* W_in  = (const float*)d_in[1];
    const float* b_in  = (const float*)d_in[2];
    const float* w0    = (const float*)d_in[3];
    const float* b0    = (const float*)d_in[4];
    const float* w1    = (const float*)d_in[5];
    const float* b1    = (const float*)d_in[6];
    const float* W_ctx = (const float*)d_in[7];
    const float* b_ctx = (const float*)d_in[8];
    const float* W_out = (const float*)d_in[9];
    const float* b_out = (const float*)d_in[10];
    float* out = (float*)d_out;

    cudaFuncSetAttribute(k_gemm_proj, cudaFuncAttributeMaxDynamicSharedMemorySize, DYN_SMEM);
    cudaFuncSetAttribute(k_gemm_mod,  cudaFuncAttributeMaxDynamicSharedMemorySize, DYN_SMEM);
    cudaFuncSetAttribute(k_gemm_out,  cudaFuncAttributeMaxDynamicSharedMemorySize, DYN_SMEM);

    // weight/input prep (fp16 hi/lo for B operands, fp16 for A operand)
    {
        __half *wh, *wl;
        cudaGetSymbolAddress((void**)&wh, g_WinT_hi);
        cudaGetSymbolAddress((void**)&wl, g_WinT_lo);
        k_transpose_split<<<dim3(NPW/32, 32), dim3(32, 8)>>>(W_in, Psz, Psz, wh, wl);
        cudaGetSymbolAddress((void**)&wh, g_WoutT_hi);
        cudaGetSymbolAddress((void**)&wl, g_WoutT_lo);
        k_transpose_split<<<dim3(32, 32), dim3(32, 8)>>>(W_out, Dsz, Dsz, wh, wl);
        cudaGetSymbolAddress((void**)&wh, g_Wctx_hi);
        cudaGetSymbolAddress((void**)&wl, g_Wctx_lo);
        k_split4h<<<(int)(((long)Dsz*Dsz/4 + 255)/256), 256>>>(W_ctx, wh, wl, (long)Dsz*Dsz/4);
        __half* ah;
        cudaGetSymbolAddress((void**)&ah, g_Ain);
        k_cvt4<<<(int)(((long)Msz*Dsz/4 + 255)/256), 256>>>(input, ah, (long)Msz*Dsz/4);
    }
    // gates (fp32, independent of proj GEMM)
    k_gates<<<Msz, 256>>>(input, W_in, b_in);
    // proj GEMM -> query/ctx
    k_gemm_proj<<<dim3(NPW/TN, Msz/TM), 256, DYN_SMEM>>>(b_in);
    // conv chain (context_all in-place in g_ctx)
    k_conv<<<Bsz * Dsz, 256>>>(w0, b0, w1, b1);
    // context transpose -> fp16 A operand
    k_ctxT_cvt<<<dim3(Ssz/32, Dsz/32, Bsz), dim3(32, 8)>>>();
    // modulator GEMM (+ query multiply; qmod fp16 into g_Ain)
    k_gemm_mod<<<dim3(Dsz/TN, Msz/TM), 256, DYN_SMEM>>>(b_ctx);
    // out GEMM
    k_gemm_out<<<dim3(Dsz/TN, Msz/TM), 256, DYN_SMEM>>>(b_out, out);
}

// round 17
// speedup vs baseline: 2.8873x; 1.4678x over previous
#include <cuda_runtime.h>
#include <cuda_fp16.h>
#include <math.h>
#include <stdint.h>

// ---------------- problem constants ----------------------------------------
#define Bsz 8
#define Ssz 4096
#define Dsz 1024
#define Psz 2051              // 2*D + FL + 1
#define NPW 2048              // proj N handled by GEMM (gates done separately)
#define Msz (Bsz*Ssz)         // 32768

// ---------------- GEMM tiling (mma.sync fp16 1-pass, CTA 128x256) ------------
#define TM 128
#define TN 256
#define KSLAB 64
#define NSLABS 16             // K=1024 / 64
#define ROWB 144              // smem row stride: 64 fp16 (128B) + 16B pad
#define A_OFF 0               // A tile: 128*144 = 18432
#define B_OFF 18432           // B tile: 256*144 = 36864
#define STAGE_BYTES 55296     // A + B
#define CSW 260               // Cs fp32 stride (query/out staging):  128*260*4 = 133120
#define CSTW 132              // CsT fp32 stride (ctx transpose):     256*132*4 = 135168
// DYN_SMEM must cover BOTH the 2-stage pipeline AND the largest epilogue buffer.
#define DYN_SMEM 135168       // max(2*STAGE_BYTES=110592, Cs=133120, CsT=135168)

// ---------------- scratch (device globals) -----------------------------------
__device__ __half g_Ain [(long)Msz*Dsz];         // input fp16 (later qmod fp16)
__device__ __half g_Ctx16[(long)Msz*Dsz];        // contextT fp16 (b*s, c)
__device__ float g_query[(long)Msz*Dsz];         // (b, s, d) natural
__device__ float g_ctx  [(long)Bsz*Dsz*Ssz];     // (b, d, s); context_all in place
__device__ float g_gates[(long)Bsz*3*Ssz];       // (b, 3, s)
__device__ __half g_WinT [(long)NPW*Dsz];        // W_in^T fp16 (n, k)
__device__ __half g_Wctx [(long)Dsz*Dsz];        // W_ctx fp16 (o, c) natural
__device__ __half g_WoutT[(long)Dsz*Dsz];        // W_out^T fp16 (n, k)

// ---------------- PTX helpers -------------------------------------------------
__device__ __forceinline__ uint32_t smem_u32(const void* p) {
    uint32_t a;
    asm("{ .reg .u64 t; cvta.to.shared.u64 t, %1; cvt.u32.u64 %0, t; }" : "=r"(a) : "l"(p));
    return a;
}
#define CP16(s, g) \
    asm volatile("cp.async.cg.shared.global [%0], [%1], 16;" :: "r"(s), "l"(g) : "memory")
#define CP_COMMIT() asm volatile("cp.async.commit_group;" ::: "memory")
#define CP_WAIT0()  asm volatile("cp.async.wait_group 0;" ::: "memory")
#define CP_WAIT1()  asm volatile("cp.async.wait_group 1;" ::: "memory")

#define LDSM4(r0, r1, r2, r3, a) \
    asm volatile("ldmatrix.sync.aligned.m8n8.x4.shared.b16 {%0,%1,%2,%3}, [%4];" \
                 : "=r"(r0), "=r"(r1), "=r"(r2), "=r"(r3) : "r"(a))
#define MMA16816(d, a, b) \
    asm volatile("mma.sync.aligned.m16n8k16.row.col.f32.f16.f16.f32 " \
                 "{%0,%1,%2,%3}, {%4,%5,%6,%7}, {%8,%9}, {%0,%1,%2,%3};" \
                 : "+f"((d)[0]), "+f"((d)[1]), "+f"((d)[2]), "+f"((d)[3]) \
                 : "r"((a)[0]), "r"((a)[1]), "r"((a)[2]), "r"((a)[3]), \
                   "r"((b)[0]), "r"((b)[1]))

__device__ __forceinline__ float gelu_f(float x) {
    return 0.5f * x * (1.0f + erff(x * 0.70710678118654752f));
}
__device__ __forceinline__ uint32_t pack2h(float v0, float v1) {
    __half a = __float2half(v0), b = __float2half(v1);
    return (uint32_t)__half_as_ushort(a) | ((uint32_t)__half_as_ushort(b) << 16);
}

// ---------------- fp16 1-pass mainloop (acc[4][8][4], 8 warps) ----------------
__device__ __forceinline__ void fp16_mainloop(
    const __half* __restrict__ A, const __half* __restrict__ B,
    long m0, long n0, uint32_t sb, float acc[4][8][4])
{
    const int tid = threadIdx.x;
    const int l = tid & 31, w = tid >> 5;
    const int wm = w >> 2, wn = w & 3;
    const int r_ = tid >> 3, u_ = tid & 7;

#define LOAD_SLAB(s, buf) do {                                                  \
        const long kb = (long)(s) * KSLAB;                                      \
        const uint32_t st = sb + (buf) * STAGE_BYTES;                           \
        _Pragma("unroll")                                                       \
        for (int it = 0; it < 4; it++) {                                        \
            const int r = it * 32 + r_;                                         \
            const uint32_t so = (uint32_t)(r * ROWB + u_ * 16);                 \
            const long ga = (m0 + r) * 1024 + kb + u_ * 8;                      \
            CP16(st + A_OFF + so, A + ga);                                      \
        }                                                                       \
        _Pragma("unroll")                                                       \
        for (int it = 0; it < 8; it++) {                                        \
            const int r = it * 32 + r_;                                         \
            const uint32_t so = (uint32_t)(r * ROWB + u_ * 16);                 \
            const long gb = (n0 + r) * 1024 + kb + u_ * 8;                      \
            CP16(st + B_OFF + so, B + gb);                                      \
        }                                                                       \
    } while (0)

    const uint32_t aoff = (uint32_t)((wm * 64 + (l & 15)) * ROWB + (l >> 4) * 16);
    const uint32_t boff = (uint32_t)((wn * 64 + ((l >> 4) * 8) + (l & 7)) * ROWB
                                     + ((l >> 3) & 1) * 16);

    LOAD_SLAB(0, 0); CP_COMMIT();
    for (int s = 0; s < NSLABS; s++) {
        if (s < NSLABS - 1) { LOAD_SLAB(s + 1, (s + 1) & 1); CP_COMMIT(); CP_WAIT1(); }
        else                { CP_WAIT0(); }
        __syncthreads();

        const uint32_t st = sb + (s & 1) * STAGE_BYTES;
        const uint32_t ab = st + A_OFF + aoff;
        const uint32_t bb = st + B_OFF + boff;
#pragma unroll
        for (int ks = 0; ks < 4; ks++) {
            uint32_t bh[8][2];
#pragma unroll
            for (int fp = 0; fp < 4; fp++) {
                LDSM4(bh[2*fp][0], bh[2*fp][1], bh[2*fp+1][0], bh[2*fp+1][1],
                      bb + fp * (16 * ROWB) + ks * 32);
            }
#pragma unroll
            for (int fm = 0; fm < 4; fm++) {
                uint32_t ah[4];
                LDSM4(ah[0], ah[1], ah[2], ah[3], ab + fm * (16 * ROWB) + ks * 32);
#pragma unroll
                for (int fn = 0; fn < 8; fn++) {
                    MMA16816(acc[fm][fn], ah, bh[fn]);
                }
            }
        }
        __syncthreads();
    }
#undef LOAD_SLAB
}

// stage acc -> Cs[128][CSW] fp32, bias added
__device__ __forceinline__ void stage_acc(
    float* Cs, float acc[4][8][4], const float* __restrict__ bias, long n0)
{
    const int tid = threadIdx.x;
    const int l = tid & 31, w = tid >> 5;
    const int wm = w >> 2, wn = w & 3;
#pragma unroll
    for (int fm = 0; fm < 4; fm++)
#pragma unroll
        for (int fn = 0; fn < 8; fn++) {
            const int row = wm * 64 + fm * 16 + (l >> 2);
            const int col = wn * 64 + fn * 8 + (l & 3) * 2;
            const float bv0 = __ldg(&bias[n0 + col]);
            const float bv1 = __ldg(&bias[n0 + col + 1]);
            Cs[row * CSW + col]           = acc[fm][fn][0] + bv0;
            Cs[row * CSW + col + 1]       = acc[fm][fn][1] + bv1;
            Cs[(row + 8) * CSW + col]     = acc[fm][fn][2] + bv0;
            Cs[(row + 8) * CSW + col + 1] = acc[fm][fn][3] + bv1;
        }
}

// stage acc transposed -> CsT[256][CSTW], bias added
__device__ __forceinline__ void stage_acc_T(
    float* CsT, float acc[4][8][4], const float* __restrict__ bias, long n0)
{
    const int tid = threadIdx.x;
    const int l = tid & 31, w = tid >> 5;
    const int wm = w >> 2, wn = w & 3;
#pragma unroll
    for (int fm = 0; fm < 4; fm++)
#pragma unroll
        for (int fn = 0; fn < 8; fn++) {
            const int row = wm * 64 + fm * 16 + (l >> 2);
            const int col = wn * 64 + fn * 8 + (l & 3) * 2;
            const float bv0 = __ldg(&bias[n0 + col]);
            const float bv1 = __ldg(&bias[n0 + col + 1]);
            CsT[col * CSTW + row]           = acc[fm][fn][0] + bv0;
            CsT[(col + 1) * CSTW + row]     = acc[fm][fn][1] + bv1;
            CsT[col * CSTW + row + 8]       = acc[fm][fn][2] + bv0;
            CsT[(col + 1) * CSTW + row + 8] = acc[fm][fn][3] + bv1;
        }
}

// ---------------- GEMM 1: proj (query + ctx regions only) ---------------------
__global__ void __launch_bounds__(256, 1)
k_gemm_proj(const float* __restrict__ b_in)
{
    extern __shared__ char dynsm[];
    const uint32_t sb = smem_u32(dynsm);
    float acc[4][8][4] = {};
    const long m0 = (long)blockIdx.y * TM;
    const long n0 = (long)blockIdx.x * TN;

    fp16_mainloop(g_Ain, g_WinT, m0, n0, sb, acc);

    const int tid = threadIdx.x;
    const long b = m0 >> 12;
    const int s0 = (int)(m0 & 4095);

    if (n0 < 1024) {
        float* Cs = (float*)dynsm;
        stage_acc(Cs, acc, b_in, n0);
        __syncthreads();
#pragma unroll
        for (int it = 0; it < 32; it++) {
            const int idx = it * 256 + tid;
            const int row = idx >> 6, c4 = (idx & 63) * 4;
            float4 v = *(float4*)&Cs[row * CSW + c4];
            *(float4*)&g_query[(m0 + row) * 1024 + n0 + c4] = v;
        }
    } else {
        float* CsT = (float*)dynsm;
        stage_acc_T(CsT, acc, b_in, n0);
        __syncthreads();
#pragma unroll
        for (int it = 0; it < 32; it++) {
            const int idx = it * 256 + tid;
            const int col = idx >> 5, u4 = (idx & 31) * 4;
            float4 v = *(float4*)&CsT[col * CSTW + u4];
            const long d = (n0 - 1024) + col;
            *(float4*)&g_ctx[((b << 10) + d) * 4096 + s0 + u4] = v;
        }
    }
}

// ---------------- gates: fp32 SIMT dots (3 cols of W_in) ----------------------
__global__ void __launch_bounds__(256)
k_gates(const float* __restrict__ input, const float* __restrict__ W_in,
        const float* __restrict__ b_in)
{
    __shared__ float red[3][8];
    const int tid = threadIdx.x;
    const long m = blockIdx.x;             // 0..32767
    const float* row = input + m * 1024;
    float a0 = 0.f, a1 = 0.f, a2 = 0.f;
#pragma unroll
    for (int it = 0; it < 4; it++) {
        const int k = it * 256 + tid;
        const float x = row[k];
        const float* wr = W_in + (long)k * Psz + 2048;
        a0 += x * wr[0]; a1 += x * wr[1]; a2 += x * wr[2];
    }
#pragma unroll
    for (int off = 16; off > 0; off >>= 1) {
        a0 += __shfl_down_sync(0xffffffffu, a0, off);
        a1 += __shfl_down_sync(0xffffffffu, a1, off);
        a2 += __shfl_down_sync(0xffffffffu, a2, off);
    }
    if ((tid & 31) == 0) {
        red[0][tid >> 5] = a0; red[1][tid >> 5] = a1; red[2][tid >> 5] = a2;
    }
    __syncthreads();
    if (tid < 3) {
        float t = 0.f;
#pragma unroll
        for (int ww = 0; ww < 8; ww++) t += red[tid][ww];
        const long b = m >> 12, s = m & 4095;
        g_gates[(b * 3 + tid) * 4096 + s] = t + b_in[2048 + tid];
    }
}

// ---------------- GEMM 2: modulator + query multiply ---------------------------
__global__ void __launch_bounds__(256, 1)
k_gemm_mod(const float* __restrict__ b_ctx)
{
    extern __shared__ char dynsm[];
    const uint32_t sb = smem_u32(dynsm);
    float acc[4][8][4] = {};
    const long m0 = (long)blockIdx.y * TM;
    const long n0 = (long)blockIdx.x * TN;

    fp16_mainloop(g_Ctx16, g_Wctx, m0, n0, sb, acc);

    float* Cs = (float*)dynsm;
    stage_acc(Cs, acc, b_ctx, n0);
    __syncthreads();

    const int tid = threadIdx.x;
#pragma unroll
    for (int it = 0; it < 32; it++) {
        const int idx = it * 256 + tid;
        const int row = idx >> 6, c4 = (idx & 63) * 4;
        const long m = m0 + row;
        const long o = n0 + c4;
        float4 c = *(float4*)&Cs[row * CSW + c4];
        float4 q = *(const float4*)&g_query[m * 1024 + o];
        uint2 hh = make_uint2(pack2h(c.x * q.x, c.y * q.y),
                              pack2h(c.z * q.z, c.w * q.w));
        *(uint2*)&g_Ain[m * 1024 + o] = hh;
    }
}

// ---------------- GEMM 3: out --------------------------------------------------
__global__ void __launch_bounds__(256, 1)
k_gemm_out(const float* __restrict__ b_out, float* __restrict__ out)
{
    extern __shared__ char dynsm[];
    const uint32_t sb = smem_u32(dynsm);
    float acc[4][8][4] = {};
    const long m0 = (long)blockIdx.y * TM;
    const long n0 = (long)blockIdx.x * TN;

    fp16_mainloop(g_Ain, g_WoutT, m0, n0, sb, acc);

    float* Cs = (float*)dynsm;
    stage_acc(Cs, acc, b_out, n0);
    __syncthreads();

    const int tid = threadIdx.x;
#pragma unroll
    for (int it = 0; it < 32; it++) {
        const int idx = it * 256 + tid;
        const int row = idx >> 6, c4 = (idx & 63) * 4;
        float4 v = *(float4*)&Cs[row * CSW + c4];
        *(float4*)&out[(m0 + row) * 1024 + n0 + c4] = v;
    }
}

// ---------------- prep kernels -------------------------------------------------
// fp32 -> fp16 elementwise
__global__ void k_cvt4(const float* __restrict__ src, __half* __restrict__ dst, long n4)
{
    long i = (long)blockIdx.x * blockDim.x + threadIdx.x;
    if (i >= n4) return;
    float4 v = *(const float4*)(src + i * 4);
    uint2 hh = make_uint2(pack2h(v.x, v.y), pack2h(v.z, v.w));
    *(uint2*)(dst + i * 4) = hh;
}

// transpose W[k][n] (ldW cols, 1024 k-rows) -> T[n][k] fp16; n >= validN -> 0
__global__ void k_transpose_cvt(const float* __restrict__ W, int ldW, int validN,
                                __half* __restrict__ T)
{
    __shared__ float t[32][33];
    const int n0 = blockIdx.x * 32, k0 = blockIdx.y * 32;
    const int tx = threadIdx.x, ty = threadIdx.y;   // 32 x 8
#pragma unroll
    for (int i = 0; i < 4; i++) {
        const int k = k0 + ty + i * 8, n = n0 + tx;
        t[tx][ty + i * 8] = (n < validN) ? W[(long)k * ldW + n] : 0.0f;
    }
    __syncthreads();
#pragma unroll
    for (int i = 0; i < 4; i++) {
        const int n = n0 + ty + i * 8, k = k0 + tx;
        T[(long)n * 1024 + k] = __float2half(t[ty + i * 8][tx]);
    }
}

// context (b, c, s) fp32 -> ctxT (b*s, c) fp16
__global__ void k_ctxT_cvt()
{
    __shared__ float t[32][33];
    const int s0 = blockIdx.x * 32, c0 = blockIdx.y * 32, b = blockIdx.z;
    const int tx = threadIdx.x, ty = threadIdx.y;   // 32 x 8
#pragma unroll
    for (int i = 0; i < 4; i++) {
        const int c = c0 + ty + i * 8, s = s0 + tx;
        t[ty + i * 8][tx] = g_ctx[((long)b * 1024 + c) * 4096 + s];
    }
    __syncthreads();
#pragma unroll
    for (int i = 0; i < 4; i++) {
        const int s = s0 + ty + i * 8, c = c0 + tx;
        g_Ctx16[((long)b * 4096 + s) * 1024 + c] = __float2half(t[tx][ty + i * 8]);
    }
}

// ---------------- conv chain (validated) ----------------------------------------
__global__ void __launch_bounds__(256)
k_conv(const float* __restrict__ w0, const float* __restrict__ b0,
       const float* __restrict__ w1, const float* __restrict__ b1)
{
    __shared__ float sx[8 + Ssz + 8];
    __shared__ float sc0[8 + Ssz + 9];
    __shared__ float warpsum[8];
    __shared__ float s_gval;

    const int tid = threadIdx.x;
    const int blk = blockIdx.x;
    const int b = blk >> 10;
    const int d = blk & 1023;

    float* row = g_ctx + ((long)b * Dsz + d) * Ssz;
#pragma unroll
    for (int i = 0; i < 4; i++) {
        const int e = (i * 256 + tid) * 4;
        *(float4*)&sx[8 + e] = *(const float4*)&row[e];
    }
    if (tid < 8) sx[tid] = 0.0f;
    if (tid < 8) sx[8 + Ssz + tid] = 0.0f;
    if (tid < 8) sc0[tid] = 0.0f;
    if (tid < 9) sc0[8 + Ssz + tid] = 0.0f;

    float rw0[14];
#pragma unroll
    for (int k = 0; k < 14; k++) rw0[k] = w0[d * 14 + k];
    const float bb0 = b0[d];
    __syncthreads();
#pragma unroll
    for (int i = 0; i < 16; i++) {
        const int s = i * 256 + tid;
        float a = bb0;
#pragma unroll
        for (int k = 0; k < 14; k++) a += rw0[k] * sx[s + 2 + k];
        sc0[8 + s] = gelu_f(a);
    }
    float rw1[18];
#pragma unroll
    for (int k = 0; k < 18; k++) rw1[k] = w1[d * 18 + k];
    const float bb1 = b1[d];
    __syncthreads();
    float c1v[16];
    float lsum = 0.0f;
#pragma unroll
    for (int i = 0; i < 16; i++) {
        const int s = i * 256 + tid;
        float a = bb1;
#pragma unroll
        for (int k = 0; k < 18; k++) a += rw1[k] * sc0[s + k];
        c1v[i] = gelu_f(a);
        lsum += c1v[i];
    }
    float v = lsum;
#pragma unroll
    for (int off = 16; off > 0; off >>= 1) v += __shfl_down_sync(0xffffffffu, v, off);
    if ((tid & 31) == 0) warpsum[tid >> 5] = v;
    __syncthreads();
    if (tid == 0) {
        float t = 0.0f;
#pragma unroll
        for (int w = 0; w < 8; w++) t += warpsum[w];
        s_gval = gelu_f(t * (1.0f / (float)Ssz));
    }
    __syncthreads();
    const float gmean = s_gval;

    const float* gg0 = g_gates + ((long)b * 3 + 0) * Ssz;
    const float* gg1 = g_gates + ((long)b * 3 + 1) * Ssz;
    const float* gg2 = g_gates + ((long)b * 3 + 2) * Ssz;
#pragma unroll
    for (int i = 0; i < 16; i++) {
        const int s = i * 256 + tid;
        row[s] = sc0[8 + s] * gg0[s] + c1v[i] * gg1[s] + gmean * gg2[s];
    }
}

// ---------------- launch --------------------------------------------------------
extern "C" void kernel_launch(void* const* d_in, const int* in_sizes, int n_in,
                              void* d_out, int out_size)
{
    const float* input = (const float*)d_in[0];
    const float* W_in  = (const float*)d_in[1];
    const float* b_in  = (const float*)d_in[2];
    const float* w0    = (const float*)d_in[3];
    const float* b0    = (const float*)d_in[4];
    const float* w1    = (const float*)d_in[5];
    const float* b1    = (const float*)d_in[6];
    const float* W_ctx = (const float*)d_in[7];
    const float* b_ctx = (const float*)d_in[8];
    const float* W_out = (const float*)d_in[9];
    const float* b_out = (const float*)d_in[10];
    float* out = (float*)d_out;

    cudaFuncSetAttribute(k_gemm_proj, cudaFuncAttributeMaxDynamicSharedMemorySize, DYN_SMEM);
    cudaFuncSetAttribute(k_gemm_mod,  cudaFuncAttributeMaxDynamicSharedMemorySize, DYN_SMEM);
    cudaFuncSetAttribute(k_gemm_out,  cudaFuncAttributeMaxDynamicSharedMemorySize, DYN_SMEM);

    // weight/input prep (fp16 conversions / transposes)
    {
        __half* wp;
        cudaGetSymbolAddress((void**)&wp, g_WinT);
        k_transpose_cvt<<<dim3(NPW/32, 32), dim3(32, 8)>>>(W_in, Psz, Psz, wp);
        cudaGetSymbolAddress((void**)&wp, g_WoutT);
        k_transpose_cvt<<<dim3(32, 32), dim3(32, 8)>>>(W_out, Dsz, Dsz, wp);
        cudaGetSymbolAddress((void**)&wp, g_Wctx);
        k_cvt4<<<(int)(((long)Dsz*Dsz/4 + 255)/256), 256>>>(W_ctx, wp, (long)Dsz*Dsz/4);
        cudaGetSymbolAddress((void**)&wp, g_Ain);
        k_cvt4<<<(int)(((long)Msz*Dsz/4 + 255)/256), 256>>>(input, wp, (long)Msz*Dsz/4);
    }
    // gates (fp32, independent of proj GEMM)
    k_gates<<<Msz, 256>>>(input, W_in, b_in);
    // proj GEMM -> query/ctx
    k_gemm_proj<<<dim3(NPW/TN, Msz/TM), 256, DYN_SMEM>>>(b_in);
    // conv chain (context_all in-place in g_ctx)
    k_conv<<<Bsz * Dsz, 256>>>(w0, b0, w1, b1);
    // context transpose -> fp16 A operand
    k_ctxT_cvt<<<dim3(Ssz/32, Dsz/32, Bsz), dim3(32, 8)>>>();
    // modulator GEMM (+ query multiply; qmod fp16 into g_Ain)
    k_gemm_mod<<<dim3(Dsz/TN, Msz/TM), 256, DYN_SMEM>>>(b_ctx);
    // out GEMM
    k_gemm_out<<<dim3(Dsz/TN, Msz/TM), 256, DYN_SMEM>>>(b_out, out);
}